// round 2
// baseline (speedup 1.0000x reference)
#include <cuda_runtime.h>
#include <cuda_bf16.h>
#include <math.h>

// ---------------- problem constants ----------------
#define BB 4
#define HH 64
#define WW 64
#define NN 4096          // HH*WW
#define CC 256
#define H2 4             // heads per branch
#define DD 32            // head dim
#define N1 1024          // (H/2)*(W/2)
#define SCALE 0.17677669529663687f  // 1/sqrt(32)

// ---------------- scratch (device globals; no allocation allowed) ----------------
__device__ float g_q1 [BB*NN*128];
__device__ float g_q2 [BB*NN*128];
__device__ float g_kv2[BB*NN*256];
__device__ float g_lin[BB*NN*256];    // lepe linear
__device__ float g_lepe[BB*NN*256];   // lepe after dwconv
__device__ float g_xcol[BB*N1*1024];  // im2col for sr conv
__device__ float g_srwt[1024*256];    // transposed sr weight
__device__ float g_xs [BB*N1*256];    // sr conv out -> LN+gelu in place
__device__ float g_kv1[BB*N1*256];
__device__ float g_att[BB*NN*256];    // x1 in [0,128), x2 in [128,256)
__device__ float g_gacc[BB*N1];       // attn1 prob column sums
__device__ float g_lmacc[BB*256*16];  // attn2 prob column sums

// ---------------- zero accumulators ----------------
__global__ void zero_kernel(float* a, int na, float* b, int nb) {
    int i = blockIdx.x * blockDim.x + threadIdx.x;
    if (i < na) a[i] = 0.f;
    if (i < nb) b[i] = 0.f;
}

// ---------------- generic tiled fp32 GEMM ----------------
// C[m,n] = ( sum_k (A[m,k] (+A2[m,k])) * B[k,n] + bias[n] ) * oscale
// A: MxK row-major, B: KxN row-major. M%64==0, N%64==0, K%16==0.
__global__ __launch_bounds__(256) void gemm_kernel(
    const float* __restrict__ A, const float* __restrict__ A2,
    const float* __restrict__ Bw, const float* __restrict__ bias,
    float* __restrict__ C, int M, int K, int Nn, float oscale)
{
    __shared__ float As[16][64];
    __shared__ float Bs[16][64];
    const int tid = threadIdx.x;
    const int tx = tid & 15, ty = tid >> 4;
    const int n0 = blockIdx.x * 64, m0 = blockIdx.y * 64;

    float acc[4][4];
#pragma unroll
    for (int i = 0; i < 4; ++i)
#pragma unroll
        for (int j = 0; j < 4; ++j) acc[i][j] = 0.f;

    const int ar = tid >> 2;              // 0..63
    const int ac = (tid & 3) << 2;        // 0,4,8,12
    const int br = tid >> 4;              // 0..15
    const int bc = (tid & 15) << 2;       // 0..60

    for (int kk = 0; kk < K; kk += 16) {
        float4 a4 = *reinterpret_cast<const float4*>(&A[(size_t)(m0 + ar) * K + kk + ac]);
        if (A2) {
            float4 b4 = *reinterpret_cast<const float4*>(&A2[(size_t)(m0 + ar) * K + kk + ac]);
            a4.x += b4.x; a4.y += b4.y; a4.z += b4.z; a4.w += b4.w;
        }
        As[ac + 0][ar] = a4.x; As[ac + 1][ar] = a4.y;
        As[ac + 2][ar] = a4.z; As[ac + 3][ar] = a4.w;

        *reinterpret_cast<float4*>(&Bs[br][bc]) =
            *reinterpret_cast<const float4*>(&Bw[(size_t)(kk + br) * Nn + n0 + bc]);
        __syncthreads();

#pragma unroll
        for (int k = 0; k < 16; ++k) {
            float4 av = *reinterpret_cast<const float4*>(&As[k][ty << 2]);
            float4 bv = *reinterpret_cast<const float4*>(&Bs[k][tx << 2]);
            float a[4] = {av.x, av.y, av.z, av.w};
            float b[4] = {bv.x, bv.y, bv.z, bv.w};
#pragma unroll
            for (int i = 0; i < 4; ++i)
#pragma unroll
                for (int j = 0; j < 4; ++j) acc[i][j] += a[i] * b[j];
        }
        __syncthreads();
    }

#pragma unroll
    for (int i = 0; i < 4; ++i) {
        int m = m0 + (ty << 2) + i;
        int n = n0 + (tx << 2);
        float4 o;
        o.x = (acc[i][0] + bias[n + 0]) * oscale;
        o.y = (acc[i][1] + bias[n + 1]) * oscale;
        o.z = (acc[i][2] + bias[n + 2]) * oscale;
        o.w = (acc[i][3] + bias[n + 3]) * oscale;
        *reinterpret_cast<float4*>(&C[(size_t)m * Nn + n]) = o;
    }
}

// ---------------- depthwise 3x3 conv (lepe), padding 1 ----------------
__global__ void dwconv_kernel(const float* __restrict__ lin,
                              const float* __restrict__ cw,
                              const float* __restrict__ cb,
                              float* __restrict__ outp)
{
    int idx = blockIdx.x * blockDim.x + threadIdx.x;  // BB*NN*CC
    int c = idx & 255;
    int n = (idx >> 8) & 4095;
    int b = idx >> 20;
    int y = n >> 6, x = n & 63;
    float acc = cb[c];
#pragma unroll
    for (int dy = 0; dy < 3; ++dy) {
        int yy = y + dy - 1;
        if ((unsigned)yy >= 64u) continue;
#pragma unroll
        for (int dx = 0; dx < 3; ++dx) {
            int xx = x + dx - 1;
            if ((unsigned)xx >= 64u) continue;
            acc += lin[((size_t)(b << 12) + (yy << 6) + xx) * 256 + c] * cw[c * 9 + dy * 3 + dx];
        }
    }
    outp[idx] = acc;
}

// ---------------- im2col for sr conv (2x2 stride 2) ----------------
// xcol[(b*1024+m)*1024 + (di*2+dj)*256 + c] = x[b, (2i+di)*64 + 2j+dj, c]
__global__ void im2col_kernel(const float* __restrict__ x, float* __restrict__ xcol)
{
    int idx = blockIdx.x * blockDim.x + threadIdx.x;  // BB*1024*1024
    int c = idx & 255;
    int f = (idx >> 8) & 3;
    int m = (idx >> 10) & 1023;
    int b = idx >> 20;
    int di = f >> 1, dj = f & 1;
    int i = m >> 5, j = m & 31;
    int n = ((i << 1) + di) * 64 + (j << 1) + dj;
    xcol[idx] = x[((size_t)(b << 12) + n) * 256 + c];
}

// wt[f*256 + o] = sr_w[o, c, di, dj] with f = (di*2+dj)*256 + c
__global__ void srwt_kernel(const float* __restrict__ srw, float* __restrict__ wt)
{
    int idx = blockIdx.x * blockDim.x + threadIdx.x;  // 1024*256
    int o = idx & 255;
    int f = idx >> 8;
    int c = f & 255;
    int q = f >> 8;
    wt[idx] = srw[(o << 10) + (c << 2) + q];
}

// ---------------- LayerNorm + exact GELU (in place), one block per row ----------------
__global__ void lngelu_kernel(float* __restrict__ xs,
                              const float* __restrict__ w, const float* __restrict__ b)
{
    int r = blockIdx.x;
    int t = threadIdx.x;
    float v = xs[(size_t)r * 256 + t];
    float s = v, s2 = v * v;
#pragma unroll
    for (int o = 16; o; o >>= 1) {
        s  += __shfl_xor_sync(0xffffffffu, s,  o);
        s2 += __shfl_xor_sync(0xffffffffu, s2, o);
    }
    __shared__ float ws[8], ws2[8];
    if ((t & 31) == 0) { ws[t >> 5] = s; ws2[t >> 5] = s2; }
    __syncthreads();
    float ts = 0.f, ts2 = 0.f;
#pragma unroll
    for (int i = 0; i < 8; ++i) { ts += ws[i]; ts2 += ws2[i]; }
    float mean = ts * (1.f / 256.f);
    float var = ts2 * (1.f / 256.f) - mean * mean;
    float y = (v - mean) * rsqrtf(var + 1e-5f) * w[t] + b[t];
    xs[(size_t)r * 256 + t] = 0.5f * y * (1.0f + erff(y * 0.70710678118654752f));
}

// ---------------- branch 1: SR global attention ----------------
// grid: (256 query tiles of 16, 16 b*h), block 512 (16 warps = 16 queries)
__global__ __launch_bounds__(512) void attn1_kernel(
    const float* __restrict__ q1, const float* __restrict__ kv1,
    float* __restrict__ att_out, float* __restrict__ gacc)
{
    extern __shared__ float sm[];
    float* sc   = sm;                  // [16][1024]
    float* kbuf = sm + 16 * 1024;      // [256][33]
    float* sq   = kbuf + 256 * 33;     // [16][32]

    const int bh = blockIdx.y;
    const int b = bh >> 2, h = bh & 3;
    const int q0 = blockIdx.x << 4;
    const int tid = threadIdx.x, warp = tid >> 5, lane = tid & 31;

    sq[tid] = q1[((size_t)(b * 4096 + q0 + warp)) * 128 + h * 32 + lane];
    __syncthreads();

    float qr[32];
#pragma unroll
    for (int dd = 0; dd < 32; ++dd) qr[dd] = sq[warp * 32 + dd];

    // scores
    for (int ch = 0; ch < 4; ++ch) {
        __syncthreads();
        for (int e = tid; e < 256 * 32; e += 512) {
            int j = e >> 5, dd = e & 31;
            kbuf[j * 33 + dd] = kv1[((size_t)(b * 1024 + (ch << 8) + j)) * 256 + h * 32 + dd];
        }
        __syncthreads();
#pragma unroll
        for (int i = 0; i < 8; ++i) {
            int j = (i << 5) + lane;
            const float* kr = &kbuf[j * 33];
            float s = 0.f;
#pragma unroll
            for (int dd = 0; dd < 32; ++dd) s += qr[dd] * kr[dd];
            sc[warp * 1024 + (ch << 8) + j] = s * SCALE;
        }
    }
    __syncthreads();

    // softmax (warp owns its row)
    float loc[32];
    float mx = -1e30f;
#pragma unroll
    for (int i = 0; i < 32; ++i) { loc[i] = sc[warp * 1024 + (i << 5) + lane]; mx = fmaxf(mx, loc[i]); }
#pragma unroll
    for (int o = 16; o; o >>= 1) mx = fmaxf(mx, __shfl_xor_sync(0xffffffffu, mx, o));
    float sum = 0.f;
#pragma unroll
    for (int i = 0; i < 32; ++i) { loc[i] = __expf(loc[i] - mx); sum += loc[i]; }
#pragma unroll
    for (int o = 16; o; o >>= 1) sum += __shfl_xor_sync(0xffffffffu, sum, o);
    float inv = 1.f / sum;
#pragma unroll
    for (int i = 0; i < 32; ++i) sc[warp * 1024 + (i << 5) + lane] = loc[i] * inv;
    __syncthreads();

    // g accumulation: column sums over the 16 queries of this tile
    {
        float cs0 = 0.f, cs1 = 0.f;
#pragma unroll
        for (int qq = 0; qq < 16; ++qq) {
            cs0 += sc[qq * 1024 + tid];
            cs1 += sc[qq * 1024 + 512 + tid];
        }
        atomicAdd(&gacc[(b << 10) + tid], cs0);
        atomicAdd(&gacc[(b << 10) + 512 + tid], cs1);
    }

    // AV
    float acc = 0.f;
    const float* row = &sc[warp * 1024];
    for (int ch = 0; ch < 4; ++ch) {
        __syncthreads();
        for (int e = tid; e < 256 * 32; e += 512) {
            int j = e >> 5, dd = e & 31;
            kbuf[j * 33 + dd] = kv1[((size_t)(b * 1024 + (ch << 8) + j)) * 256 + 128 + h * 32 + dd];
        }
        __syncthreads();
#pragma unroll 8
        for (int j = 0; j < 256; ++j) {
            acc += row[(ch << 8) + j] * kbuf[j * 33 + lane];
        }
    }
    att_out[((size_t)(b * 4096 + q0 + warp)) * 256 + h * 32 + lane] = acc;
}

// ---------------- branch 2: 4x4 window attention ----------------
// block: 128 threads = 8 windows x 16 threads (thread = query token)
__global__ __launch_bounds__(128) void attn2_kernel(
    const float* __restrict__ q2, const float* __restrict__ kv2,
    float* __restrict__ att_out, float* __restrict__ lmacc)
{
    __shared__ float ks[8][16][33];
    __shared__ float vs[8][16][33];
    __shared__ float ps[8][16][17];
    const int tid = threadIdx.x;
    const int g = tid >> 4, t = tid & 15;
    const int w = (blockIdx.x << 3) + g;
    const int b = w >> 10, h = (w >> 8) & 3, win = w & 255;
    const int wy = win >> 4, wx = win & 15;
    const int n = ((wy << 2) + (t >> 2)) * 64 + (wx << 2) + (t & 3);

    const float* kvrow = &kv2[((size_t)(b * 4096 + n)) * 256 + h * 32];
    const float* qrow  = &q2 [((size_t)(b * 4096 + n)) * 128 + h * 32];
    float qr[32];
#pragma unroll
    for (int dd = 0; dd < 32; ++dd) {
        ks[g][t][dd] = kvrow[dd];
        vs[g][t][dd] = kvrow[128 + dd];
        qr[dd] = qrow[dd];
    }
    __syncthreads();

    float s[16];
    float mx = -1e30f;
#pragma unroll
    for (int m = 0; m < 16; ++m) {
        float a = 0.f;
#pragma unroll
        for (int dd = 0; dd < 32; ++dd) a += qr[dd] * ks[g][m][dd];
        s[m] = a * SCALE;
        mx = fmaxf(mx, s[m]);
    }
    float sum = 0.f;
#pragma unroll
    for (int m = 0; m < 16; ++m) { s[m] = __expf(s[m] - mx); sum += s[m]; }
    float inv = 1.f / sum;

    float o[32];
#pragma unroll
    for (int dd = 0; dd < 32; ++dd) o[dd] = 0.f;
#pragma unroll
    for (int m = 0; m < 16; ++m) {
        float p = s[m] * inv;
        ps[g][t][m] = p;
#pragma unroll
        for (int dd = 0; dd < 32; ++dd) o[dd] += p * vs[g][m][dd];
    }
    float* orow = &att_out[((size_t)(b * 4096 + n)) * 256 + 128 + h * 32];
#pragma unroll
    for (int dd = 0; dd < 32; ++dd) orow[dd] = o[dd];
    __syncthreads();

    float cs = 0.f;
#pragma unroll
    for (int qq = 0; qq < 16; ++qq) cs += ps[g][qq][t];
    atomicAdd(&lmacc[((b << 8) + win) * 16 + t], cs);
}

// ---------------- mask assembly ----------------
__global__ void mask_kernel(const float* __restrict__ gacc,
                            const float* __restrict__ lmacc,
                            float* __restrict__ out)
{
    int idx = blockIdx.x * blockDim.x + threadIdx.x;  // BB*NN
    int b = idx >> 12, n = idx & 4095;
    int y = n >> 6, x = n & 63;
    float gv = gacc[(b << 10) + ((y >> 1) << 5) + (x >> 1)] * (1.f / 16384.f);
    float lv = lmacc[((b << 8) + ((y >> 2) << 4) + (x >> 2)) * 16 + ((y & 3) << 2) + (x & 3)] * (1.f / 64.f);
    float m = gv + lv;
    out[4194304 + (b << 12) + (y << 6) + x] = m;   // mask1
    out[4210688 + (b << 12) + (x << 6) + y] = m;   // mask2 (transposed)
}

// ---------------- host launcher ----------------
extern "C" void kernel_launch(void* const* d_in, const int* in_sizes, int n_in,
                              void* d_out, int out_size)
{
    const float* x        = (const float*)d_in[0];
    const float* q1_w     = (const float*)d_in[1];
    const float* q1_b     = (const float*)d_in[2];
    const float* kv1_w    = (const float*)d_in[3];
    const float* kv1_b    = (const float*)d_in[4];
    const float* q2_w     = (const float*)d_in[5];
    const float* q2_b     = (const float*)d_in[6];
    const float* kv2_w    = (const float*)d_in[7];
    const float* kv2_b    = (const float*)d_in[8];
    const float* lepe_w   = (const float*)d_in[9];
    const float* lepe_b   = (const float*)d_in[10];
    const float* lepe_cw  = (const float*)d_in[11];
    const float* lepe_cb  = (const float*)d_in[12];
    const float* sr_w     = (const float*)d_in[13];
    const float* sr_b     = (const float*)d_in[14];
    const float* norm_w   = (const float*)d_in[15];
    const float* norm_b   = (const float*)d_in[16];
    const float* proj_w   = (const float*)d_in[17];
    const float* proj_b   = (const float*)d_in[18];
    float* out = (float*)d_out;

    float *p_q1, *p_q2, *p_kv2, *p_lin, *p_lepe, *p_xcol, *p_srwt, *p_xs, *p_kv1, *p_att, *p_g, *p_lm;
    cudaGetSymbolAddress((void**)&p_q1,   g_q1);
    cudaGetSymbolAddress((void**)&p_q2,   g_q2);
    cudaGetSymbolAddress((void**)&p_kv2,  g_kv2);
    cudaGetSymbolAddress((void**)&p_lin,  g_lin);
    cudaGetSymbolAddress((void**)&p_lepe, g_lepe);
    cudaGetSymbolAddress((void**)&p_xcol, g_xcol);
    cudaGetSymbolAddress((void**)&p_srwt, g_srwt);
    cudaGetSymbolAddress((void**)&p_xs,   g_xs);
    cudaGetSymbolAddress((void**)&p_kv1,  g_kv1);
    cudaGetSymbolAddress((void**)&p_att,  g_att);
    cudaGetSymbolAddress((void**)&p_g,    g_gacc);
    cudaGetSymbolAddress((void**)&p_lm,   g_lmacc);

    const int attn1_smem = (16 * 1024 + 256 * 33 + 16 * 32) * sizeof(float);
    cudaFuncSetAttribute(attn1_kernel, cudaFuncAttributeMaxDynamicSharedMemorySize, attn1_smem);

    // zero the atomic accumulators
    zero_kernel<<<64, 256>>>(p_g, BB * N1, p_lm, BB * 256 * 16);

    // token-parallel linears from x: M=16384, K=256
    gemm_kernel<<<dim3(2, 256), 256>>>(x, nullptr, q1_w,   q1_b,   p_q1,  16384, 256, 128, 1.f);
    gemm_kernel<<<dim3(2, 256), 256>>>(x, nullptr, q2_w,   q2_b,   p_q2,  16384, 256, 128, 1.f);
    gemm_kernel<<<dim3(4, 256), 256>>>(x, nullptr, kv2_w,  kv2_b,  p_kv2, 16384, 256, 256, 1.f);
    gemm_kernel<<<dim3(4, 256), 256>>>(x, nullptr, lepe_w, lepe_b, p_lin, 16384, 256, 256, 1.f);

    // lepe depthwise conv
    dwconv_kernel<<<16384, 256>>>(p_lin, lepe_cw, lepe_cb, p_lepe);

    // sr conv = im2col + GEMM (K=1024)
    im2col_kernel<<<16384, 256>>>(x, p_xcol);
    srwt_kernel<<<1024, 256>>>(sr_w, p_srwt);
    gemm_kernel<<<dim3(4, 64), 256>>>(p_xcol, nullptr, p_srwt, sr_b, p_xs, 4096, 1024, 256, 1.f);

    // LN + GELU, then kv1
    lngelu_kernel<<<4096, 256>>>(p_xs, norm_w, norm_b);
    gemm_kernel<<<dim3(4, 64), 256>>>(p_xs, nullptr, kv1_w, kv1_b, p_kv1, 4096, 256, 256, 1.f);

    // attention branches
    attn1_kernel<<<dim3(256, 16), 512, attn1_smem>>>(p_q1, p_kv1, p_att, p_g);
    attn2_kernel<<<512, 128>>>(p_q2, p_kv2, p_att, p_lm);

    // final projection: out = 2*((att + lepe) @ proj_w + proj_b)
    gemm_kernel<<<dim3(4, 256), 256>>>(p_att, p_lepe, proj_w, proj_b, out, 16384, 256, 256, 2.f);

    // masks
    mask_kernel<<<64, 256>>>(p_g, p_lm, out);
}

// round 3
// speedup vs baseline: 2.0679x; 2.0679x over previous
#include <cuda_runtime.h>
#include <cuda_bf16.h>
#include <math.h>

// ---------------- problem constants ----------------
#define BB 4
#define NN 4096
#define CC 256
#define N1 1024
#define SCALE 0.17677669529663687f  // 1/sqrt(32)

// ---------------- scratch ----------------
__device__ float g_q1 [BB*NN*128];
__device__ float g_q2 [BB*NN*128];
__device__ float g_kv2[BB*NN*256];
__device__ float g_lin[BB*NN*256];
__device__ float g_lepe[BB*NN*256];
__device__ float g_xcol[BB*N1*1024];
__device__ float g_srwt[1024*256];
__device__ float g_xs [BB*N1*256];
__device__ float g_kv1[BB*N1*256];
__device__ float g_att[BB*NN*256];
__device__ float g_gacc[BB*N1];
__device__ float g_lmacc[BB*256*16];

// ---------------- tf32 helpers ----------------
__device__ __forceinline__ unsigned f2tf(float f) {
    unsigned u;
    asm("cvt.rna.tf32.f32 %0, %1;" : "=r"(u) : "f"(f));
    return u;
}

__device__ __forceinline__ void mma8(float* d, const unsigned* a, const unsigned* b) {
    asm volatile(
        "mma.sync.aligned.m16n8k8.row.col.f32.tf32.tf32.f32 "
        "{%0,%1,%2,%3}, {%4,%5,%6,%7}, {%8,%9}, {%0,%1,%2,%3};"
        : "+f"(d[0]), "+f"(d[1]), "+f"(d[2]), "+f"(d[3])
        : "r"(a[0]), "r"(a[1]), "r"(a[2]), "r"(a[3]), "r"(b[0]), "r"(b[1]));
}

// ---------------- zero accumulators ----------------
__global__ void zero_kernel(float* a, int na, float* b, int nb) {
    int i = blockIdx.x * blockDim.x + threadIdx.x;
    if (i < na) a[i] = 0.f;
    if (i < nb) b[i] = 0.f;
}

// ---------------- tf32 tensor-core GEMM ----------------
// C[m,n] = ( sum_k (A[m,k](+A2[m,k])) * B[k,n] + bias[n] ) * oscale
// Block tile 128x128, 8 warps (2x4), warp tile 64x32, k-chunk 32.
__global__ __launch_bounds__(256, 2) void gemm_tc(
    const float* __restrict__ A, const float* __restrict__ A2,
    const float* __restrict__ Bw, const float* __restrict__ bias,
    float* __restrict__ C, int M, int K, int Nn, float oscale)
{
    __shared__ unsigned As[128 * 36];   // [m][k], stride 36 -> conflict-free frag loads
    __shared__ unsigned Bs[32 * 136];   // [k][n], stride 136 -> conflict-free frag loads
    __shared__ float biass[128];
    const int tid = threadIdx.x, warp = tid >> 5, lane = tid & 31;
    const int m0 = blockIdx.y * 128, n0 = blockIdx.x * 128;
    const int wm = (warp & 1) * 64, wn = (warp >> 1) * 32;

    if (tid < 128) biass[tid] = bias[n0 + tid];

    float acc[4][4][4];
#pragma unroll
    for (int i = 0; i < 4; ++i)
#pragma unroll
        for (int j = 0; j < 4; ++j)
#pragma unroll
            for (int k = 0; k < 4; ++k) acc[i][j][k] = 0.f;

    const int am = tid >> 1, akb = (tid & 1) * 16;
    const int bk = tid >> 3, bnb = (tid & 7) * 16;

    for (int kk = 0; kk < K; kk += 32) {
        __syncthreads();
#pragma unroll
        for (int i = 0; i < 4; ++i) {
            float4 v = *(const float4*)&A[(size_t)(m0 + am) * K + kk + akb + i * 4];
            if (A2) {
                float4 w = *(const float4*)&A2[(size_t)(m0 + am) * K + kk + akb + i * 4];
                v.x += w.x; v.y += w.y; v.z += w.z; v.w += w.w;
            }
            unsigned* p = &As[am * 36 + akb + i * 4];
            p[0] = f2tf(v.x); p[1] = f2tf(v.y); p[2] = f2tf(v.z); p[3] = f2tf(v.w);
        }
#pragma unroll
        for (int i = 0; i < 4; ++i) {
            float4 v = *(const float4*)&Bw[(size_t)(kk + bk) * Nn + n0 + bnb + i * 4];
            unsigned* p = &Bs[bk * 136 + bnb + i * 4];
            p[0] = f2tf(v.x); p[1] = f2tf(v.y); p[2] = f2tf(v.z); p[3] = f2tf(v.w);
        }
        __syncthreads();

#pragma unroll
        for (int ks = 0; ks < 4; ++ks) {
            unsigned a[4][4], b[4][2];
#pragma unroll
            for (int mt = 0; mt < 4; ++mt) {
                int r = wm + mt * 16 + (lane >> 2), c = ks * 8 + (lane & 3);
                a[mt][0] = As[r * 36 + c];
                a[mt][1] = As[(r + 8) * 36 + c];
                a[mt][2] = As[r * 36 + c + 4];
                a[mt][3] = As[(r + 8) * 36 + c + 4];
            }
#pragma unroll
            for (int nt = 0; nt < 4; ++nt) {
                int n = wn + nt * 8 + (lane >> 2), kr = ks * 8 + (lane & 3);
                b[nt][0] = Bs[kr * 136 + n];
                b[nt][1] = Bs[(kr + 4) * 136 + n];
            }
#pragma unroll
            for (int mt = 0; mt < 4; ++mt)
#pragma unroll
                for (int nt = 0; nt < 4; ++nt) mma8(acc[mt][nt], a[mt], b[nt]);
        }
    }

#pragma unroll
    for (int mt = 0; mt < 4; ++mt) {
        int r = m0 + wm + mt * 16 + (lane >> 2);
#pragma unroll
        for (int nt = 0; nt < 4; ++nt) {
            int c = wn + nt * 8 + (lane & 3) * 2;
            float2 v0 = make_float2((acc[mt][nt][0] + biass[c]) * oscale,
                                    (acc[mt][nt][1] + biass[c + 1]) * oscale);
            float2 v1 = make_float2((acc[mt][nt][2] + biass[c]) * oscale,
                                    (acc[mt][nt][3] + biass[c + 1]) * oscale);
            *(float2*)&C[(size_t)r * Nn + n0 + c] = v0;
            *(float2*)&C[(size_t)(r + 8) * Nn + n0 + c] = v1;
        }
    }
}

// ---------------- branch 1: SR global attention, tf32 mma ----------------
// block = 32 queries x one (b,h); full 1024-key score rows in smem (exact softmax + g sums).
#define S_STR 1036
#define QS_OFF (32 * S_STR)            // 33152
#define KV_OFF (QS_OFF + 32 * 36)      // 34304
#define OP_OFF (KV_OFF + 128 * 36)     // 38912
#define A1_SMEM_FLOATS (OP_OFF + 8 * 544)  // 43264 floats = 173056 B

__global__ __launch_bounds__(256) void attn1_tc(
    const float* __restrict__ q1, const float* __restrict__ kv1,
    float* __restrict__ att_out, float* __restrict__ gacc)
{
    extern __shared__ float sm[];
    float* S = sm;
    unsigned* qs = (unsigned*)(sm + QS_OFF);
    unsigned* kv = (unsigned*)(sm + KV_OFF);
    float* op = sm + OP_OFF;

    const int tid = threadIdx.x, warp = tid >> 5, lane = tid & 31;
    const int bh = blockIdx.y, b = bh >> 2, h = bh & 3;
    const int q0 = blockIdx.x * 32;
    const int wq = warp & 1, wk = warp >> 1;

    // stage Q (32x32) as tf32
    {
        int q = tid >> 3, d4 = (tid & 7) * 4;
        float4 v = *(const float4*)&q1[(size_t)(b * 4096 + q0 + q) * 128 + h * 32 + d4];
        unsigned* p = &qs[q * 36 + d4];
        p[0] = f2tf(v.x); p[1] = f2tf(v.y); p[2] = f2tf(v.z); p[3] = f2tf(v.w);
    }
    __syncthreads();

    unsigned qa[4][4];
#pragma unroll
    for (int ks = 0; ks < 4; ++ks) {
        int r = wq * 16 + (lane >> 2), c = ks * 8 + (lane & 3);
        qa[ks][0] = qs[r * 36 + c];
        qa[ks][1] = qs[(r + 8) * 36 + c];
        qa[ks][2] = qs[r * 36 + c + 4];
        qa[ks][3] = qs[(r + 8) * 36 + c + 4];
    }

    // ---- S = (Q K^T) * scale, chunks of 128 keys ----
    for (int ch = 0; ch < 8; ++ch) {
        __syncthreads();
        {
            int jj = tid >> 1, db = (tid & 1) * 16;
#pragma unroll
            for (int i = 0; i < 4; ++i) {
                float4 v = *(const float4*)&kv1[(size_t)(b * 1024 + ch * 128 + jj) * 256 + h * 32 + db + i * 4];
                unsigned* p = &kv[jj * 36 + db + i * 4];
                p[0] = f2tf(v.x); p[1] = f2tf(v.y); p[2] = f2tf(v.z); p[3] = f2tf(v.w);
            }
        }
        __syncthreads();

        float c4[4][4];
#pragma unroll
        for (int nt = 0; nt < 4; ++nt)
#pragma unroll
            for (int k = 0; k < 4; ++k) c4[nt][k] = 0.f;

#pragma unroll
        for (int ks = 0; ks < 4; ++ks) {
#pragma unroll
            for (int nt = 0; nt < 4; ++nt) {
                int n = wk * 32 + nt * 8 + (lane >> 2), dr = ks * 8 + (lane & 3);
                unsigned bb[2] = { kv[n * 36 + dr], kv[n * 36 + dr + 4] };
                mma8(c4[nt], qa[ks], bb);
            }
        }
#pragma unroll
        for (int nt = 0; nt < 4; ++nt) {
            int r = wq * 16 + (lane >> 2);
            int col = ch * 128 + wk * 32 + nt * 8 + (lane & 3) * 2;
            *(float2*)&S[r * S_STR + col] = make_float2(c4[nt][0] * SCALE, c4[nt][1] * SCALE);
            *(float2*)&S[(r + 8) * S_STR + col] = make_float2(c4[nt][2] * SCALE, c4[nt][3] * SCALE);
        }
    }
    __syncthreads();

    // ---- softmax: warp owns 4 rows ----
#pragma unroll
    for (int rr = 0; rr < 4; ++rr) {
        int r = warp * 4 + rr;
        float v[32];
        float mx = -1e30f;
#pragma unroll
        for (int i = 0; i < 32; ++i) { v[i] = S[r * S_STR + lane + 32 * i]; mx = fmaxf(mx, v[i]); }
#pragma unroll
        for (int o = 16; o; o >>= 1) mx = fmaxf(mx, __shfl_xor_sync(0xffffffffu, mx, o));
        float ssum = 0.f;
#pragma unroll
        for (int i = 0; i < 32; ++i) { v[i] = __expf(v[i] - mx); ssum += v[i]; }
#pragma unroll
        for (int o = 16; o; o >>= 1) ssum += __shfl_xor_sync(0xffffffffu, ssum, o);
        float inv = 1.f / ssum;
#pragma unroll
        for (int i = 0; i < 32; ++i) S[r * S_STR + lane + 32 * i] = v[i] * inv;
    }
    __syncthreads();

    // ---- column sums of P -> g accumulator ----
    {
        float cs[4] = {0.f, 0.f, 0.f, 0.f};
        for (int r = 0; r < 32; ++r)
#pragma unroll
            for (int j = 0; j < 4; ++j) cs[j] += S[r * S_STR + tid + 256 * j];
#pragma unroll
        for (int j = 0; j < 4; ++j) atomicAdd(&gacc[(b << 10) + tid + 256 * j], cs[j]);
    }

    // ---- O = P V, warps split keys (wr), accumulate partials ----
    float o4[4][4];
#pragma unroll
    for (int nt = 0; nt < 4; ++nt)
#pragma unroll
        for (int k = 0; k < 4; ++k) o4[nt][k] = 0.f;

    const int wr = warp >> 1;
    for (int ch = 0; ch < 8; ++ch) {
        __syncthreads();
        {
            int jj = tid >> 1, db = (tid & 1) * 16;
#pragma unroll
            for (int i = 0; i < 4; ++i) {
                float4 v = *(const float4*)&kv1[(size_t)(b * 1024 + ch * 128 + jj) * 256 + 128 + h * 32 + db + i * 4];
                unsigned* p = &kv[jj * 36 + db + i * 4];
                p[0] = f2tf(v.x); p[1] = f2tf(v.y); p[2] = f2tf(v.z); p[3] = f2tf(v.w);
            }
        }
        __syncthreads();

#pragma unroll
        for (int ks = 0; ks < 4; ++ks) {
            int jb = ch * 128 + wr * 32 + ks * 8;
            int r = wq * 16 + (lane >> 2), c = jb + (lane & 3);
            unsigned a[4] = { f2tf(S[r * S_STR + c]),       f2tf(S[(r + 8) * S_STR + c]),
                              f2tf(S[r * S_STR + c + 4]),   f2tf(S[(r + 8) * S_STR + c + 4]) };
            int jl = wr * 32 + ks * 8 + (lane & 3);
#pragma unroll
            for (int nt = 0; nt < 4; ++nt) {
                int d = nt * 8 + (lane >> 2);
                unsigned bb[2] = { kv[jl * 36 + d], kv[(jl + 4) * 36 + d] };
                mma8(o4[nt], a, bb);
            }
        }
    }

    // partial O -> smem, reduce over 4 key-split warps
#pragma unroll
    for (int nt = 0; nt < 4; ++nt) {
        int rr = lane >> 2, col = nt * 8 + (lane & 3) * 2;
        *(float2*)&op[warp * 544 + rr * 34 + col] = make_float2(o4[nt][0], o4[nt][1]);
        *(float2*)&op[warp * 544 + (rr + 8) * 34 + col] = make_float2(o4[nt][2], o4[nt][3]);
    }
    __syncthreads();
#pragma unroll
    for (int i = 0; i < 4; ++i) {
        int idx = tid + 256 * i;
        int q = idx >> 5, d = idx & 31;
        int wq2 = q >> 4, ql = q & 15;
        float s = op[(0 + wq2) * 544 + ql * 34 + d] + op[(2 + wq2) * 544 + ql * 34 + d]
                + op[(4 + wq2) * 544 + ql * 34 + d] + op[(6 + wq2) * 544 + ql * 34 + d];
        att_out[(size_t)(b * 4096 + q0 + q) * 256 + h * 32 + d] = s;
    }
}

// ---------------- depthwise 3x3 conv (lepe), padding 1 ----------------
__global__ void dwconv_kernel(const float* __restrict__ lin,
                              const float* __restrict__ cw,
                              const float* __restrict__ cb,
                              float* __restrict__ outp)
{
    int idx = blockIdx.x * blockDim.x + threadIdx.x;
    int c = idx & 255;
    int n = (idx >> 8) & 4095;
    int b = idx >> 20;
    int y = n >> 6, x = n & 63;
    float acc = cb[c];
#pragma unroll
    for (int dy = 0; dy < 3; ++dy) {
        int yy = y + dy - 1;
        if ((unsigned)yy >= 64u) continue;
#pragma unroll
        for (int dx = 0; dx < 3; ++dx) {
            int xx = x + dx - 1;
            if ((unsigned)xx >= 64u) continue;
            acc += lin[((size_t)(b << 12) + (yy << 6) + xx) * 256 + c] * cw[c * 9 + dy * 3 + dx];
        }
    }
    outp[idx] = acc;
}

// ---------------- im2col for sr conv (2x2 stride 2) ----------------
__global__ void im2col_kernel(const float* __restrict__ x, float* __restrict__ xcol)
{
    int idx = blockIdx.x * blockDim.x + threadIdx.x;
    int c = idx & 255;
    int f = (idx >> 8) & 3;
    int m = (idx >> 10) & 1023;
    int b = idx >> 20;
    int di = f >> 1, dj = f & 1;
    int i = m >> 5, j = m & 31;
    int n = ((i << 1) + di) * 64 + (j << 1) + dj;
    xcol[idx] = x[((size_t)(b << 12) + n) * 256 + c];
}

__global__ void srwt_kernel(const float* __restrict__ srw, float* __restrict__ wt)
{
    int idx = blockIdx.x * blockDim.x + threadIdx.x;
    int o = idx & 255;
    int f = idx >> 8;
    int c = f & 255;
    int q = f >> 8;
    wt[idx] = srw[(o << 10) + (c << 2) + q];
}

// ---------------- LayerNorm + exact GELU ----------------
__global__ void lngelu_kernel(float* __restrict__ xs,
                              const float* __restrict__ w, const float* __restrict__ b)
{
    int r = blockIdx.x;
    int t = threadIdx.x;
    float v = xs[(size_t)r * 256 + t];
    float s = v, s2 = v * v;
#pragma unroll
    for (int o = 16; o; o >>= 1) {
        s  += __shfl_xor_sync(0xffffffffu, s,  o);
        s2 += __shfl_xor_sync(0xffffffffu, s2, o);
    }
    __shared__ float ws[8], ws2[8];
    if ((t & 31) == 0) { ws[t >> 5] = s; ws2[t >> 5] = s2; }
    __syncthreads();
    float ts = 0.f, ts2 = 0.f;
#pragma unroll
    for (int i = 0; i < 8; ++i) { ts += ws[i]; ts2 += ws2[i]; }
    float mean = ts * (1.f / 256.f);
    float var = ts2 * (1.f / 256.f) - mean * mean;
    float y = (v - mean) * rsqrtf(var + 1e-5f) * w[t] + b[t];
    xs[(size_t)r * 256 + t] = 0.5f * y * (1.0f + erff(y * 0.70710678118654752f));
}

// ---------------- branch 2: 4x4 window attention (fp32, small) ----------------
__global__ __launch_bounds__(128) void attn2_kernel(
    const float* __restrict__ q2, const float* __restrict__ kv2,
    float* __restrict__ att_out, float* __restrict__ lmacc)
{
    __shared__ float ks[8][16][33];
    __shared__ float vs[8][16][33];
    __shared__ float ps[8][16][17];
    const int tid = threadIdx.x;
    const int g = tid >> 4, t = tid & 15;
    const int w = (blockIdx.x << 3) + g;
    const int b = w >> 10, h = (w >> 8) & 3, win = w & 255;
    const int wy = win >> 4, wx = win & 15;
    const int n = ((wy << 2) + (t >> 2)) * 64 + (wx << 2) + (t & 3);

    const float* kvrow = &kv2[((size_t)(b * 4096 + n)) * 256 + h * 32];
    const float* qrow  = &q2 [((size_t)(b * 4096 + n)) * 128 + h * 32];
    float qr[32];
#pragma unroll
    for (int dd = 0; dd < 32; ++dd) {
        ks[g][t][dd] = kvrow[dd];
        vs[g][t][dd] = kvrow[128 + dd];
        qr[dd] = qrow[dd];
    }
    __syncthreads();

    float s[16];
    float mx = -1e30f;
#pragma unroll
    for (int m = 0; m < 16; ++m) {
        float a = 0.f;
#pragma unroll
        for (int dd = 0; dd < 32; ++dd) a += qr[dd] * ks[g][m][dd];
        s[m] = a * SCALE;
        mx = fmaxf(mx, s[m]);
    }
    float sum = 0.f;
#pragma unroll
    for (int m = 0; m < 16; ++m) { s[m] = __expf(s[m] - mx); sum += s[m]; }
    float inv = 1.f / sum;

    float o[32];
#pragma unroll
    for (int dd = 0; dd < 32; ++dd) o[dd] = 0.f;
#pragma unroll
    for (int m = 0; m < 16; ++m) {
        float p = s[m] * inv;
        ps[g][t][m] = p;
#pragma unroll
        for (int dd = 0; dd < 32; ++dd) o[dd] += p * vs[g][m][dd];
    }
    float* orow = &att_out[((size_t)(b * 4096 + n)) * 256 + 128 + h * 32];
#pragma unroll
    for (int dd = 0; dd < 32; ++dd) orow[dd] = o[dd];
    __syncthreads();

    float cs = 0.f;
#pragma unroll
    for (int qq = 0; qq < 16; ++qq) cs += ps[g][qq][t];
    atomicAdd(&lmacc[((b << 8) + win) * 16 + t], cs);
}

// ---------------- mask assembly ----------------
__global__ void mask_kernel(const float* __restrict__ gacc,
                            const float* __restrict__ lmacc,
                            float* __restrict__ out)
{
    int idx = blockIdx.x * blockDim.x + threadIdx.x;
    int b = idx >> 12, n = idx & 4095;
    int y = n >> 6, x = n & 63;
    float gv = gacc[(b << 10) + ((y >> 1) << 5) + (x >> 1)] * (1.f / 16384.f);
    float lv = lmacc[((b << 8) + ((y >> 2) << 4) + (x >> 2)) * 16 + ((y & 3) << 2) + (x & 3)] * (1.f / 64.f);
    float m = gv + lv;
    out[4194304 + (b << 12) + (y << 6) + x] = m;
    out[4210688 + (b << 12) + (x << 6) + y] = m;
}

// ---------------- host launcher ----------------
extern "C" void kernel_launch(void* const* d_in, const int* in_sizes, int n_in,
                              void* d_out, int out_size)
{
    const float* x        = (const float*)d_in[0];
    const float* q1_w     = (const float*)d_in[1];
    const float* q1_b     = (const float*)d_in[2];
    const float* kv1_w    = (const float*)d_in[3];
    const float* kv1_b    = (const float*)d_in[4];
    const float* q2_w     = (const float*)d_in[5];
    const float* q2_b     = (const float*)d_in[6];
    const float* kv2_w    = (const float*)d_in[7];
    const float* kv2_b    = (const float*)d_in[8];
    const float* lepe_w   = (const float*)d_in[9];
    const float* lepe_b   = (const float*)d_in[10];
    const float* lepe_cw  = (const float*)d_in[11];
    const float* lepe_cb  = (const float*)d_in[12];
    const float* sr_w     = (const float*)d_in[13];
    const float* sr_b     = (const float*)d_in[14];
    const float* norm_w   = (const float*)d_in[15];
    const float* norm_b   = (const float*)d_in[16];
    const float* proj_w   = (const float*)d_in[17];
    const float* proj_b   = (const float*)d_in[18];
    float* out = (float*)d_out;

    float *p_q1, *p_q2, *p_kv2, *p_lin, *p_lepe, *p_xcol, *p_srwt, *p_xs, *p_kv1, *p_att, *p_g, *p_lm;
    cudaGetSymbolAddress((void**)&p_q1,   g_q1);
    cudaGetSymbolAddress((void**)&p_q2,   g_q2);
    cudaGetSymbolAddress((void**)&p_kv2,  g_kv2);
    cudaGetSymbolAddress((void**)&p_lin,  g_lin);
    cudaGetSymbolAddress((void**)&p_lepe, g_lepe);
    cudaGetSymbolAddress((void**)&p_xcol, g_xcol);
    cudaGetSymbolAddress((void**)&p_srwt, g_srwt);
    cudaGetSymbolAddress((void**)&p_xs,   g_xs);
    cudaGetSymbolAddress((void**)&p_kv1,  g_kv1);
    cudaGetSymbolAddress((void**)&p_att,  g_att);
    cudaGetSymbolAddress((void**)&p_g,    g_gacc);
    cudaGetSymbolAddress((void**)&p_lm,   g_lmacc);

    const int a1_smem = A1_SMEM_FLOATS * (int)sizeof(float);
    cudaFuncSetAttribute(attn1_tc, cudaFuncAttributeMaxDynamicSharedMemorySize, a1_smem);

    // zero atomic accumulators
    zero_kernel<<<64, 256>>>(p_g, BB * N1, p_lm, BB * 256 * 16);

    // linears from x: M=16384, K=256
    gemm_tc<<<dim3(1, 128), 256>>>(x, nullptr, q1_w,   q1_b,   p_q1,  16384, 256, 128, 1.f);
    gemm_tc<<<dim3(1, 128), 256>>>(x, nullptr, q2_w,   q2_b,   p_q2,  16384, 256, 128, 1.f);
    gemm_tc<<<dim3(2, 128), 256>>>(x, nullptr, kv2_w,  kv2_b,  p_kv2, 16384, 256, 256, 1.f);
    gemm_tc<<<dim3(2, 128), 256>>>(x, nullptr, lepe_w, lepe_b, p_lin, 16384, 256, 256, 1.f);

    // lepe depthwise conv
    dwconv_kernel<<<16384, 256>>>(p_lin, lepe_cw, lepe_cb, p_lepe);

    // sr conv = im2col + GEMM (K=1024)
    im2col_kernel<<<16384, 256>>>(x, p_xcol);
    srwt_kernel<<<1024, 256>>>(sr_w, p_srwt);
    gemm_tc<<<dim3(2, 32), 256>>>(p_xcol, nullptr, p_srwt, sr_b, p_xs, 4096, 1024, 256, 1.f);

    // LN + GELU, then kv1
    lngelu_kernel<<<4096, 256>>>(p_xs, norm_w, norm_b);
    gemm_tc<<<dim3(2, 32), 256>>>(p_xs, nullptr, kv1_w, kv1_b, p_kv1, 4096, 256, 256, 1.f);

    // attention branches
    attn1_tc<<<dim3(128, 16), 256, a1_smem>>>(p_q1, p_kv1, p_att, p_g);
    attn2_kernel<<<512, 128>>>(p_q2, p_kv2, p_att, p_lm);

    // final projection: out = 2*((att + lepe) @ proj_w + proj_b)
    gemm_tc<<<dim3(2, 128), 256>>>(p_att, p_lepe, proj_w, proj_b, out, 16384, 256, 256, 2.f);

    // masks
    mask_kernel<<<64, 256>>>(p_g, p_lm, out);
}

// round 7
// speedup vs baseline: 2.3486x; 1.1357x over previous
#include <cuda_runtime.h>
#include <math.h>

// ---------------- problem constants ----------------
#define BB 4
#define NN 4096
#define N1 1024
#define SCALE 0.17677669529663687f  // 1/sqrt(32)

// ---------------- scratch ----------------
__device__ float g_big [BB*NN*768];   // cols: q1[0,128) q2[128,256) kv2[256,512) lin[512,768)
__device__ float g_lepe[BB*NN*256];
__device__ float g_xcol[BB*N1*1024];
__device__ float g_srwt[1024*256];
__device__ float g_xs  [BB*N1*256];
__device__ float g_kv1 [BB*N1*256];
__device__ float g_att [BB*NN*256];
__device__ float g_gacc[BB*N1];
__device__ float g_lmacc[BB*256*16];
__device__ float g_wbig[256*768];
__device__ float g_bbig[768];
__device__ float g_wkv1[256*256];
__device__ float g_wproj[256*256];

// ---------------- helpers ----------------
__device__ __forceinline__ unsigned f2tf(float f) {
    unsigned u;
    asm("cvt.rna.tf32.f32 %0, %1;" : "=r"(u) : "f"(f));
    return u;
}
__device__ __forceinline__ float f2tff(float f) { return __uint_as_float(f2tf(f)); }

__device__ __forceinline__ void mma8(float* d, const unsigned* a, const unsigned* b) {
    asm volatile(
        "mma.sync.aligned.m16n8k8.row.col.f32.tf32.tf32.f32 "
        "{%0,%1,%2,%3}, {%4,%5,%6,%7}, {%8,%9}, {%0,%1,%2,%3};"
        : "+f"(d[0]), "+f"(d[1]), "+f"(d[2]), "+f"(d[3])
        : "r"(a[0]), "r"(a[1]), "r"(a[2]), "r"(a[3]), "r"(b[0]), "r"(b[1]));
}

__device__ __forceinline__ unsigned sptr(const void* p) {
    return (unsigned)__cvta_generic_to_shared(p);
}
#define CPA(dst, src) asm volatile("cp.async.cg.shared.global [%0], [%1], 16;" :: "r"(dst), "l"(src))
#define CPC() asm volatile("cp.async.commit_group;")
#define CPW(n) asm volatile("cp.async.wait_group %0;" :: "n"(n))

// ---------------- zero accumulators ----------------
__global__ void zero_kernel(float* a, int na, float* b, int nb) {
    int i = blockIdx.x * blockDim.x + threadIdx.x;
    if (i < na) a[i] = 0.f;
    if (i < nb) b[i] = 0.f;
}

// ---------------- weight prep ----------------
__global__ void cvt_kernel(const float* __restrict__ s, float* __restrict__ d, int n) {
    int i = blockIdx.x * blockDim.x + threadIdx.x;
    if (i < n) d[i] = f2tff(s[i]);
}

__global__ void wcat_kernel(const float* __restrict__ q1w, const float* __restrict__ q2w,
                            const float* __restrict__ kv2w, const float* __restrict__ lepew,
                            const float* __restrict__ q1b, const float* __restrict__ q2b,
                            const float* __restrict__ kv2b, const float* __restrict__ lepeb,
                            float* __restrict__ wbig, float* __restrict__ bbig)
{
    int idx = blockIdx.x * blockDim.x + threadIdx.x;  // 256*768
    int j = idx % 768, k = idx / 768;
    float v;
    if (j < 128)      v = q1w[k * 128 + j];
    else if (j < 256) v = q2w[k * 128 + j - 128];
    else if (j < 512) v = kv2w[k * 256 + j - 256];
    else              v = lepew[k * 256 + j - 512];
    wbig[idx] = f2tff(v);
    if (k == 0) {
        float bv;
        if (j < 128)      bv = q1b[j];
        else if (j < 256) bv = q2b[j - 128];
        else if (j < 512) bv = kv2b[j - 256];
        else              bv = lepeb[j - 512];
        bbig[j] = bv;
    }
}

// wt[f*256 + o] = sr_w[o, c, di, dj], f = (di*2+dj)*256 + c, rounded to tf32
__global__ void srwt_kernel(const float* __restrict__ srw, float* __restrict__ wt)
{
    int idx = blockIdx.x * blockDim.x + threadIdx.x;  // 1024*256
    int o = idx & 255;
    int f = idx >> 8;
    int c = f & 255;
    int q = f >> 8;
    wt[idx] = f2tff(srw[(o << 10) + (c << 2) + q]);
}

// ---------------- pipelined tf32 GEMM ----------------
// C = ((A (+A2)) @ Bw + bias) * oscale ; Bw pre-rounded tf32 (cp.async pass-through).
// Block 128x128, 8 warps (2x4), warp 64x32, kc=32, B double-buffered via cp.async,
// A register double-buffered (cvt.rna at STS).
template<int FUSE>
__global__ __launch_bounds__(256, 2) void gemm_tc(
    const float* __restrict__ A, const float* __restrict__ A2,
    const float* __restrict__ Bw, const float* __restrict__ bias,
    float* __restrict__ C, int M, int K, int Nn, float oscale, int oround)
{
    extern __shared__ float smx[];
    float* As = smx;                   // [2][128*36]
    float* Bs = smx + 2 * 4608;        // [2][32*136]
    float* biass = smx + 2 * 4608 + 2 * 4352;  // [128]
    const int tid = threadIdx.x, warp = tid >> 5, lane = tid & 31;
    const int m0 = blockIdx.y * 128, n0 = blockIdx.x * 128;
    const int wm = (warp & 1) * 64, wn = (warp >> 1) * 32;
    if (tid < 128) biass[tid] = bias[n0 + tid];

    float acc[4][4][4];
#pragma unroll
    for (int i = 0; i < 4; ++i)
#pragma unroll
        for (int j = 0; j < 4; ++j)
#pragma unroll
            for (int k = 0; k < 4; ++k) acc[i][j][k] = 0.f;

    const int am = tid >> 1, akb = (tid & 1) * 16;
    const int bk = tid >> 3, bnb = (tid & 7) * 16;
    const float* Ap  = A + (size_t)(m0 + am) * K + akb;
    const float* A2p = FUSE ? (A2 + (size_t)(m0 + am) * K + akb) : (const float*)0;
    const float* Bp  = Bw + (size_t)bk * Nn + n0 + bnb;
    const unsigned BsW = sptr(Bs) + (bk * 136 + bnb) * 4;

    float4 ar[4], ar2[4];
#pragma unroll
    for (int i = 0; i < 4; ++i) ar[i] = *(const float4*)(Ap + i * 4);
    if (FUSE) {
#pragma unroll
        for (int i = 0; i < 4; ++i) ar2[i] = *(const float4*)(A2p + i * 4);
    }
#pragma unroll
    for (int i = 0; i < 4; ++i) CPA(BsW + i * 16, Bp + i * 4);
    CPC();

    const int nc = K >> 5;
    for (int c = 0; c < nc; ++c) {
        const int buf = c & 1;
        CPW(0);
        {
            float* dst = As + buf * 4608 + am * 36 + akb;
#pragma unroll
            for (int i = 0; i < 4; ++i) {
                float4 v = ar[i];
                if (FUSE) { float4 w = ar2[i]; v.x += w.x; v.y += w.y; v.z += w.z; v.w += w.w; }
                dst[i * 4 + 0] = f2tff(v.x); dst[i * 4 + 1] = f2tff(v.y);
                dst[i * 4 + 2] = f2tff(v.z); dst[i * 4 + 3] = f2tff(v.w);
            }
        }
        __syncthreads();
        if (c + 1 < nc) {
            const float* bp = Bp + (size_t)(c + 1) * 32 * Nn;
            unsigned w = BsW + (buf ^ 1) * (4352 * 4);
#pragma unroll
            for (int i = 0; i < 4; ++i) CPA(w + i * 16, bp + i * 4);
            CPC();
            const float* ap = Ap + (c + 1) * 32;
#pragma unroll
            for (int i = 0; i < 4; ++i) ar[i] = *(const float4*)(ap + i * 4);
            if (FUSE) {
                const float* a2p = A2p + (c + 1) * 32;
#pragma unroll
                for (int i = 0; i < 4; ++i) ar2[i] = *(const float4*)(a2p + i * 4);
            }
        }
        const float* Ab = As + buf * 4608;
        const float* Bb = Bs + buf * 4352;
#pragma unroll
        for (int ks = 0; ks < 4; ++ks) {
            unsigned a[4][4], bfr[4][2];
#pragma unroll
            for (int mt = 0; mt < 4; ++mt) {
                int r = wm + mt * 16 + (lane >> 2), cc = ks * 8 + (lane & 3);
                a[mt][0] = __float_as_uint(Ab[r * 36 + cc]);
                a[mt][1] = __float_as_uint(Ab[(r + 8) * 36 + cc]);
                a[mt][2] = __float_as_uint(Ab[r * 36 + cc + 4]);
                a[mt][3] = __float_as_uint(Ab[(r + 8) * 36 + cc + 4]);
            }
#pragma unroll
            for (int nt = 0; nt < 4; ++nt) {
                int n = wn + nt * 8 + (lane >> 2), kr = ks * 8 + (lane & 3);
                bfr[nt][0] = __float_as_uint(Bb[kr * 136 + n]);
                bfr[nt][1] = __float_as_uint(Bb[(kr + 4) * 136 + n]);
            }
#pragma unroll
            for (int mt = 0; mt < 4; ++mt)
#pragma unroll
                for (int nt = 0; nt < 4; ++nt) mma8(acc[mt][nt], a[mt], bfr[nt]);
        }
    }

#pragma unroll
    for (int mt = 0; mt < 4; ++mt) {
        int r = m0 + wm + mt * 16 + (lane >> 2);
#pragma unroll
        for (int nt = 0; nt < 4; ++nt) {
            int cc = wn + nt * 8 + (lane & 3) * 2;
            float o0 = (acc[mt][nt][0] + biass[cc]) * oscale;
            float o1 = (acc[mt][nt][1] + biass[cc + 1]) * oscale;
            float o2 = (acc[mt][nt][2] + biass[cc]) * oscale;
            float o3 = (acc[mt][nt][3] + biass[cc + 1]) * oscale;
            if (oround) { o0 = f2tff(o0); o1 = f2tff(o1); o2 = f2tff(o2); o3 = f2tff(o3); }
            *(float2*)&C[(size_t)r * Nn + n0 + cc] = make_float2(o0, o1);
            *(float2*)&C[(size_t)(r + 8) * Nn + n0 + cc] = make_float2(o2, o3);
        }
    }
}

// ---------------- branch 1: SR global attention (pipelined) ----------------
// smem (floats): S [32][1036]=33152 | qs [32][36]=1152 | kv [2][128*36]=9216 | op [8][544]=4352
#define S_STR 1036
#define A1_SMEM_FLOATS 47872

__global__ __launch_bounds__(256) void attn1_tc(
    const float* __restrict__ q1, const float* __restrict__ kv1,
    float* __restrict__ att_out, float* __restrict__ gacc)
{
    extern __shared__ float sm[];
    float* S  = sm;
    float* qs = sm + 33152;
    float* kv = sm + 34304;
    float* op = sm + 43520;

    const int tid = threadIdx.x, warp = tid >> 5, lane = tid & 31;
    const int bh = blockIdx.y, b = bh >> 2, h = bh & 3;
    const int q0 = blockIdx.x * 32;
    const int wq = warp & 1, wk = warp >> 1;

    // stage Q (pre-rounded tf32 floats, pass-through)
    {
        int q = tid >> 3, d4 = (tid & 7) * 4;
        float4 v = *(const float4*)&q1[(size_t)(b * 4096 + q0 + q) * 768 + h * 32 + d4];
        float* p = &qs[q * 36 + d4];
        p[0] = v.x; p[1] = v.y; p[2] = v.z; p[3] = v.w;
    }
    // prefetch K chunk 0
    const int jj = tid >> 1, db = (tid & 1) * 16;
    const size_t kbase = (size_t)(b * 1024) * 256 + h * 32;
    const size_t vbase = kbase + 128;
    const unsigned kvW = sptr(kv) + (jj * 36 + db) * 4;
    {
        const float* src = kv1 + kbase + (size_t)jj * 256 + db;
#pragma unroll
        for (int i = 0; i < 4; ++i) CPA(kvW + i * 16, src + i * 4);
        CPC();
    }
    __syncthreads();

    unsigned qa[4][4];
#pragma unroll
    for (int ks = 0; ks < 4; ++ks) {
        int r = wq * 16 + (lane >> 2), cc = ks * 8 + (lane & 3);
        qa[ks][0] = __float_as_uint(qs[r * 36 + cc]);
        qa[ks][1] = __float_as_uint(qs[(r + 8) * 36 + cc]);
        qa[ks][2] = __float_as_uint(qs[r * 36 + cc + 4]);
        qa[ks][3] = __float_as_uint(qs[(r + 8) * 36 + cc + 4]);
    }

    // ---- S = (Q K^T) * scale ----
    for (int ch = 0; ch < 8; ++ch) {
        const int buf = ch & 1;
        CPW(0);
        __syncthreads();
        if (ch < 7) {
            const float* src = kv1 + kbase + (size_t)((ch + 1) * 128 + jj) * 256 + db;
            unsigned w = kvW + (buf ^ 1) * (4608 * 4);
#pragma unroll
            for (int i = 0; i < 4; ++i) CPA(w + i * 16, src + i * 4);
            CPC();
        }
        const float* kb = kv + buf * 4608;
        float c4[4][4];
#pragma unroll
        for (int nt = 0; nt < 4; ++nt)
#pragma unroll
            for (int k = 0; k < 4; ++k) c4[nt][k] = 0.f;
#pragma unroll
        for (int ks = 0; ks < 4; ++ks) {
#pragma unroll
            for (int nt = 0; nt < 4; ++nt) {
                int n = wk * 32 + nt * 8 + (lane >> 2), dr = ks * 8 + (lane & 3);
                unsigned bb2[2] = { __float_as_uint(kb[n * 36 + dr]),
                                    __float_as_uint(kb[n * 36 + dr + 4]) };
                mma8(c4[nt], qa[ks], bb2);
            }
        }
#pragma unroll
        for (int nt = 0; nt < 4; ++nt) {
            int r = wq * 16 + (lane >> 2);
            int col = ch * 128 + wk * 32 + nt * 8 + (lane & 3) * 2;
            *(float2*)&S[r * S_STR + col] = make_float2(c4[nt][0] * SCALE, c4[nt][1] * SCALE);
            *(float2*)&S[(r + 8) * S_STR + col] = make_float2(c4[nt][2] * SCALE, c4[nt][3] * SCALE);
        }
    }
    __syncthreads();

    // prefetch V chunk 0 (overlaps softmax)
    {
        const float* src = kv1 + vbase + (size_t)jj * 256 + db;
#pragma unroll
        for (int i = 0; i < 4; ++i) CPA(kvW + i * 16, src + i * 4);
        CPC();
    }

    // ---- softmax: warp owns 4 rows; store P pre-rounded (tf32) ----
#pragma unroll
    for (int rr = 0; rr < 4; ++rr) {
        int r = warp * 4 + rr;
        float v[32];
        float mx = -1e30f;
#pragma unroll
        for (int i = 0; i < 32; ++i) { v[i] = S[r * S_STR + lane + 32 * i]; mx = fmaxf(mx, v[i]); }
#pragma unroll
        for (int o = 16; o; o >>= 1) mx = fmaxf(mx, __shfl_xor_sync(0xffffffffu, mx, o));
        float ssum = 0.f;
#pragma unroll
        for (int i = 0; i < 32; ++i) { v[i] = __expf(v[i] - mx); ssum += v[i]; }
#pragma unroll
        for (int o = 16; o; o >>= 1) ssum += __shfl_xor_sync(0xffffffffu, ssum, o);
        float inv = 1.f / ssum;
#pragma unroll
        for (int i = 0; i < 32; ++i) S[r * S_STR + lane + 32 * i] = f2tff(v[i] * inv);
    }
    __syncthreads();

    // ---- column sums of P -> g accumulator ----
    {
        float cs[4] = {0.f, 0.f, 0.f, 0.f};
        for (int r = 0; r < 32; ++r)
#pragma unroll
            for (int j = 0; j < 4; ++j) cs[j] += S[r * S_STR + tid + 256 * j];
#pragma unroll
        for (int j = 0; j < 4; ++j) atomicAdd(&gacc[(b << 10) + tid + 256 * j], cs[j]);
    }

    // ---- O = P V (key-split across 4 warp groups) ----
    float o4[4][4];
#pragma unroll
    for (int nt = 0; nt < 4; ++nt)
#pragma unroll
        for (int k = 0; k < 4; ++k) o4[nt][k] = 0.f;

    const int wr = warp >> 1;
    for (int ch = 0; ch < 8; ++ch) {
        const int buf = ch & 1;
        CPW(0);
        __syncthreads();
        if (ch < 7) {
            const float* src = kv1 + vbase + (size_t)((ch + 1) * 128 + jj) * 256 + db;
            unsigned w = kvW + (buf ^ 1) * (4608 * 4);
#pragma unroll
            for (int i = 0; i < 4; ++i) CPA(w + i * 16, src + i * 4);
            CPC();
        }
        const float* vb = kv + buf * 4608;
#pragma unroll
        for (int ks = 0; ks < 4; ++ks) {
            int jb = ch * 128 + wr * 32 + ks * 8;
            int r = wq * 16 + (lane >> 2), c = jb + (lane & 3);
            unsigned a[4] = { __float_as_uint(S[r * S_STR + c]),
                              __float_as_uint(S[(r + 8) * S_STR + c]),
                              __float_as_uint(S[r * S_STR + c + 4]),
                              __float_as_uint(S[(r + 8) * S_STR + c + 4]) };
            int jl = wr * 32 + ks * 8 + (lane & 3);
#pragma unroll
            for (int nt = 0; nt < 4; ++nt) {
                int d = nt * 8 + (lane >> 2);
                unsigned bb2[2] = { __float_as_uint(vb[jl * 36 + d]),
                                    __float_as_uint(vb[(jl + 4) * 36 + d]) };
                mma8(o4[nt], a, bb2);
            }
        }
    }

    // partial O -> smem, reduce over 4 key-split warps
#pragma unroll
    for (int nt = 0; nt < 4; ++nt) {
        int rr = lane >> 2, col = nt * 8 + (lane & 3) * 2;
        *(float2*)&op[warp * 544 + rr * 34 + col] = make_float2(o4[nt][0], o4[nt][1]);
        *(float2*)&op[warp * 544 + (rr + 8) * 34 + col] = make_float2(o4[nt][2], o4[nt][3]);
    }
    __syncthreads();
#pragma unroll
    for (int i = 0; i < 4; ++i) {
        int idx = tid + 256 * i;
        int q = idx >> 5, d = idx & 31;
        int wq2 = q >> 4, ql = q & 15;
        float s = op[(0 + wq2) * 544 + ql * 34 + d] + op[(2 + wq2) * 544 + ql * 34 + d]
                + op[(4 + wq2) * 544 + ql * 34 + d] + op[(6 + wq2) * 544 + ql * 34 + d];
        att_out[(size_t)(b * 4096 + q0 + q) * 256 + h * 32 + d] = s;
    }
}

// ---------------- depthwise 3x3 conv (lepe), float4 over channels ----------------
__global__ void dwconv_kernel(const float* __restrict__ lin,
                              const float* __restrict__ cw,
                              const float* __restrict__ cb,
                              float* __restrict__ outp)
{
    int idx = blockIdx.x * blockDim.x + threadIdx.x;  // BB*NN*64
    int c4 = idx & 63;
    int n = (idx >> 6) & 4095;
    int b = idx >> 18;
    int y = n >> 6, x = n & 63;
    int c = c4 << 2;
    float4 acc = make_float4(cb[c], cb[c + 1], cb[c + 2], cb[c + 3]);
#pragma unroll
    for (int dy = 0; dy < 3; ++dy) {
        int yy = y + dy - 1;
        if ((unsigned)yy >= 64u) continue;
#pragma unroll
        for (int dx = 0; dx < 3; ++dx) {
            int xx = x + dx - 1;
            if ((unsigned)xx >= 64u) continue;
            float4 v = *(const float4*)&lin[((size_t)((b << 12) + (yy << 6) + xx)) * 768 + 512 + c];
            int wi = dy * 3 + dx;
            acc.x += v.x * cw[(c + 0) * 9 + wi];
            acc.y += v.y * cw[(c + 1) * 9 + wi];
            acc.z += v.z * cw[(c + 2) * 9 + wi];
            acc.w += v.w * cw[(c + 3) * 9 + wi];
        }
    }
    *(float4*)&outp[((size_t)((b << 12) + n)) * 256 + c] = acc;
}

// ---------------- im2col (float4) ----------------
__global__ void im2col_kernel(const float* __restrict__ x, float* __restrict__ xcol)
{
    int idx = blockIdx.x * blockDim.x + threadIdx.x;  // BB*N1*256
    int c4 = idx & 63;
    int f = (idx >> 6) & 3;
    int m = (idx >> 8) & 1023;
    int b = idx >> 18;
    int di = f >> 1, dj = f & 1;
    int i = m >> 5, j = m & 31;
    int n = ((i << 1) + di) * 64 + (j << 1) + dj;
    *(float4*)&xcol[(size_t)idx * 4] =
        *(const float4*)&x[((size_t)((b << 12) + n)) * 256 + (c4 << 2)];
}

// ---------------- LayerNorm + exact GELU ----------------
__global__ void lngelu_kernel(float* __restrict__ xs,
                              const float* __restrict__ w, const float* __restrict__ b)
{
    int r = blockIdx.x;
    int t = threadIdx.x;
    float v = xs[(size_t)r * 256 + t];
    float s = v, s2 = v * v;
#pragma unroll
    for (int o = 16; o; o >>= 1) {
        s  += __shfl_xor_sync(0xffffffffu, s,  o);
        s2 += __shfl_xor_sync(0xffffffffu, s2, o);
    }
    __shared__ float ws[8], ws2[8];
    if ((t & 31) == 0) { ws[t >> 5] = s; ws2[t >> 5] = s2; }
    __syncthreads();
    float ts = 0.f, ts2 = 0.f;
#pragma unroll
    for (int i = 0; i < 8; ++i) { ts += ws[i]; ts2 += ws2[i]; }
    float mean = ts * (1.f / 256.f);
    float var = ts2 * (1.f / 256.f) - mean * mean;
    float y = (v - mean) * rsqrtf(var + 1e-5f) * w[t] + b[t];
    xs[(size_t)r * 256 + t] = 0.5f * y * (1.0f + erff(y * 0.70710678118654752f));
}

// ---------------- branch 2: 4x4 window attention ----------------
__global__ __launch_bounds__(128) void attn2_kernel(
    const float* __restrict__ big, float* __restrict__ att_out, float* __restrict__ lmacc)
{
    __shared__ float ks[8][16][33];
    __shared__ float vs[8][16][33];
    __shared__ float ps[8][16][17];
    const int tid = threadIdx.x;
    const int g = tid >> 4, t = tid & 15;
    const int w = (blockIdx.x << 3) + g;
    const int b = w >> 10, h = (w >> 8) & 3, win = w & 255;
    const int wy = win >> 4, wx = win & 15;
    const int n = ((wy << 2) + (t >> 2)) * 64 + (wx << 2) + (t & 3);

    const float* row = &big[((size_t)(b * 4096 + n)) * 768];
    float qr[32];
#pragma unroll
    for (int dd = 0; dd < 32; ++dd) {
        ks[g][t][dd] = row[256 + h * 32 + dd];
        vs[g][t][dd] = row[384 + h * 32 + dd];
        qr[dd] = row[128 + h * 32 + dd];
    }
    __syncthreads();

    float s[16];
    float mx = -1e30f;
#pragma unroll
    for (int m = 0; m < 16; ++m) {
        float a = 0.f;
#pragma unroll
        for (int dd = 0; dd < 32; ++dd) a += qr[dd] * ks[g][m][dd];
        s[m] = a * SCALE;
        mx = fmaxf(mx, s[m]);
    }
    float sum = 0.f;
#pragma unroll
    for (int m = 0; m < 16; ++m) { s[m] = __expf(s[m] - mx); sum += s[m]; }
    float inv = 1.f / sum;

    float o[32];
#pragma unroll
    for (int dd = 0; dd < 32; ++dd) o[dd] = 0.f;
#pragma unroll
    for (int m = 0; m < 16; ++m) {
        float p = s[m] * inv;
        ps[g][t][m] = p;
#pragma unroll
        for (int dd = 0; dd < 32; ++dd) o[dd] += p * vs[g][m][dd];
    }
    float* orow = &att_out[((size_t)(b * 4096 + n)) * 256 + 128 + h * 32];
#pragma unroll
    for (int dd = 0; dd < 32; ++dd) orow[dd] = o[dd];
    __syncthreads();

    float cs = 0.f;
#pragma unroll
    for (int qq = 0; qq < 16; ++qq) cs += ps[g][qq][t];
    atomicAdd(&lmacc[((b << 8) + win) * 16 + t], cs);
}

// ---------------- mask assembly ----------------
__global__ void mask_kernel(const float* __restrict__ gacc,
                            const float* __restrict__ lmacc,
                            float* __restrict__ out)
{
    int idx = blockIdx.x * blockDim.x + threadIdx.x;
    int b = idx >> 12, n = idx & 4095;
    int y = n >> 6, x = n & 63;
    float gv = gacc[(b << 10) + ((y >> 1) << 5) + (x >> 1)] * (1.f / 16384.f);
    float lv = lmacc[((b << 8) + ((y >> 2) << 4) + (x >> 2)) * 16 + ((y & 3) << 2) + (x & 3)] * (1.f / 64.f);
    float m = gv + lv;
    out[4194304 + (b << 12) + (y << 6) + x] = m;
    out[4210688 + (b << 12) + (x << 6) + y] = m;
}

// ---------------- host launcher ----------------
extern "C" void kernel_launch(void* const* d_in, const int* in_sizes, int n_in,
                              void* d_out, int out_size)
{
    const float* x        = (const float*)d_in[0];
    const float* q1_w     = (const float*)d_in[1];
    const float* q1_b     = (const float*)d_in[2];
    const float* kv1_w    = (const float*)d_in[3];
    const float* kv1_b    = (const float*)d_in[4];
    const float* q2_w     = (const float*)d_in[5];
    const float* q2_b     = (const float*)d_in[6];
    const float* kv2_w    = (const float*)d_in[7];
    const float* kv2_b    = (const float*)d_in[8];
    const float* lepe_w   = (const float*)d_in[9];
    const float* lepe_b   = (const float*)d_in[10];
    const float* lepe_cw  = (const float*)d_in[11];
    const float* lepe_cb  = (const float*)d_in[12];
    const float* sr_w     = (const float*)d_in[13];
    const float* sr_b     = (const float*)d_in[14];
    const float* norm_w   = (const float*)d_in[15];
    const float* norm_b   = (const float*)d_in[16];
    const float* proj_w   = (const float*)d_in[17];
    const float* proj_b   = (const float*)d_in[18];
    float* out = (float*)d_out;

    float *p_big, *p_lepe, *p_xcol, *p_srwt, *p_xs, *p_kv1, *p_att, *p_g, *p_lm;
    float *p_wbig, *p_bbig, *p_wkv1, *p_wproj;
    cudaGetSymbolAddress((void**)&p_big,   g_big);
    cudaGetSymbolAddress((void**)&p_lepe,  g_lepe);
    cudaGetSymbolAddress((void**)&p_xcol,  g_xcol);
    cudaGetSymbolAddress((void**)&p_srwt,  g_srwt);
    cudaGetSymbolAddress((void**)&p_xs,    g_xs);
    cudaGetSymbolAddress((void**)&p_kv1,   g_kv1);
    cudaGetSymbolAddress((void**)&p_att,   g_att);
    cudaGetSymbolAddress((void**)&p_g,     g_gacc);
    cudaGetSymbolAddress((void**)&p_lm,    g_lmacc);
    cudaGetSymbolAddress((void**)&p_wbig,  g_wbig);
    cudaGetSymbolAddress((void**)&p_bbig,  g_bbig);
    cudaGetSymbolAddress((void**)&p_wkv1,  g_wkv1);
    cudaGetSymbolAddress((void**)&p_wproj, g_wproj);

    const int gsm = (2 * 4608 + 2 * 4352 + 128) * (int)sizeof(float);  // 72192 B
    cudaFuncSetAttribute(gemm_tc<0>, cudaFuncAttributeMaxDynamicSharedMemorySize, gsm);
    cudaFuncSetAttribute(gemm_tc<1>, cudaFuncAttributeMaxDynamicSharedMemorySize, gsm);
    const int a1sm = A1_SMEM_FLOATS * (int)sizeof(float);  // 191488 B
    cudaFuncSetAttribute(attn1_tc, cudaFuncAttributeMaxDynamicSharedMemorySize, a1sm);

    // accumulators + weight prep
    zero_kernel<<<64, 256>>>(p_g, BB * N1, p_lm, BB * 256 * 16);
    wcat_kernel<<<768, 256>>>(q1_w, q2_w, kv2_w, lepe_w, q1_b, q2_b, kv2_b, lepe_b, p_wbig, p_bbig);
    cvt_kernel<<<256, 256>>>(kv1_w, p_wkv1, 256 * 256);
    cvt_kernel<<<256, 256>>>(proj_w, p_wproj, 256 * 256);
    srwt_kernel<<<1024, 256>>>(sr_w, p_srwt);

    // fused linears: x @ [q1|q2|kv2|lepe] -> g_big [16384 x 768] (rounded)
    gemm_tc<0><<<dim3(6, 128), 256, gsm>>>(x, nullptr, p_wbig, p_bbig, p_big, 16384, 256, 768, 1.f, 1);

    // lepe depthwise conv (reads lin cols [512,768) of g_big)
    dwconv_kernel<<<4096, 256>>>(p_big, lepe_cw, lepe_cb, p_lepe);

    // sr conv = im2col + GEMM (K=1024)
    im2col_kernel<<<4096, 256>>>(x, p_xcol);
    gemm_tc<0><<<dim3(2, 32), 256, gsm>>>(p_xcol, nullptr, p_srwt, sr_b, p_xs, 4096, 1024, 256, 1.f, 0);

    // LN + GELU, then kv1 (rounded for attn1 cp.async pass-through)
    lngelu_kernel<<<4096, 256>>>(p_xs, norm_w, norm_b);
    gemm_tc<0><<<dim3(2, 32), 256, gsm>>>(p_xs, nullptr, p_wkv1, kv1_b, p_kv1, 4096, 256, 256, 1.f, 1);

    // attention branches
    attn1_tc<<<dim3(128, 16), 256, a1sm>>>(p_big, p_kv1, p_att, p_g);
    attn2_kernel<<<512, 128>>>(p_big, p_att, p_lm);

    // final projection: out = 2*((att + lepe) @ proj_w + proj_b)
    gemm_tc<1><<<dim3(2, 128), 256, gsm>>>(p_att, p_lepe, p_wproj, proj_b, out, 16384, 256, 256, 2.f, 0);

    // masks
    mask_kernel<<<64, 256>>>(p_g, p_lm, out);
}

// round 11
// speedup vs baseline: 2.5379x; 1.0806x over previous
#include <cuda_runtime.h>
#include <math.h>

// ---------------- problem constants ----------------
#define BB 4
#define NN 4096
#define N1 1024
#define SCALE 0.17677669529663687f  // 1/sqrt(32)

// ---------------- scratch ----------------
__device__ float g_big [BB*NN*768];   // cols: q1[0,128) q2[128,256) kv2[256,512) lin[512,768)
__device__ float g_lepe[BB*NN*256];
__device__ float g_srwt[1024*256];
__device__ float g_xs  [BB*N1*256];
__device__ float g_kv1 [BB*N1*256];
__device__ float g_att [BB*NN*256];   // x1 in [0,128), x2 in [128,256)
__device__ float g_gacc[BB*N1];
__device__ float g_lmacc[BB*256*16];
__device__ float g_wbig[256*768];
__device__ float g_bbig[768];
__device__ float g_wkv1[256*256];
__device__ float g_wproj[256*256];

// ---------------- helpers ----------------
__device__ __forceinline__ unsigned f2tf(float f) {
    unsigned u;
    asm("cvt.rna.tf32.f32 %0, %1;" : "=r"(u) : "f"(f));
    return u;
}
__device__ __forceinline__ float f2tff(float f) { return __uint_as_float(f2tf(f)); }

__device__ __forceinline__ void mma8(float* d, const unsigned* a, const unsigned* b) {
    asm volatile(
        "mma.sync.aligned.m16n8k8.row.col.f32.tf32.tf32.f32 "
        "{%0,%1,%2,%3}, {%4,%5,%6,%7}, {%8,%9}, {%0,%1,%2,%3};"
        : "+f"(d[0]), "+f"(d[1]), "+f"(d[2]), "+f"(d[3])
        : "r"(a[0]), "r"(a[1]), "r"(a[2]), "r"(a[3]), "r"(b[0]), "r"(b[1]));
}

__device__ __forceinline__ unsigned sptr(const void* p) {
    return (unsigned)__cvta_generic_to_shared(p);
}
#define CPA(dst, src) asm volatile("cp.async.cg.shared.global [%0], [%1], 16;" :: "r"(dst), "l"(src))
#define CPC() asm volatile("cp.async.commit_group;")
#define CPW(n) asm volatile("cp.async.wait_group %0;" :: "n"(n))

// ---------------- fused prep: weight concat/cvt/transpose + accumulator zero ----------------
__global__ void prep_kernel(const float* __restrict__ q1w, const float* __restrict__ q2w,
                            const float* __restrict__ kv2w, const float* __restrict__ lepew,
                            const float* __restrict__ q1b, const float* __restrict__ q2b,
                            const float* __restrict__ kv2b, const float* __restrict__ lepeb,
                            const float* __restrict__ kv1w, const float* __restrict__ projw,
                            const float* __restrict__ srw,
                            float* __restrict__ wbig, float* __restrict__ bbig,
                            float* __restrict__ wkv1, float* __restrict__ wproj,
                            float* __restrict__ srwt,
                            float* __restrict__ gacc, float* __restrict__ lmacc)
{
    int idx = blockIdx.x * blockDim.x + threadIdx.x;   // grid 1024*256 = 262144
    // srwt: wt[f*256+o] = sr_w[o, c, di, dj], f=(di*2+dj)*256+c
    {
        int o = idx & 255, f = idx >> 8, c = f & 255, q = f >> 8;
        srwt[idx] = f2tff(srw[(o << 10) + (c << 2) + q]);
    }
    if (idx < 196608) {   // wcat: 256 x 768
        int j = idx % 768, k = idx / 768;
        float v;
        if (j < 128)      v = q1w[k * 128 + j];
        else if (j < 256) v = q2w[k * 128 + j - 128];
        else if (j < 512) v = kv2w[k * 256 + j - 256];
        else              v = lepew[k * 256 + j - 512];
        wbig[idx] = f2tff(v);
        if (k == 0) {
            float bv;
            if (j < 128)      bv = q1b[j];
            else if (j < 256) bv = q2b[j - 128];
            else if (j < 512) bv = kv2b[j - 256];
            else              bv = lepeb[j - 512];
            bbig[j] = bv;
        }
    }
    if (idx < 65536) {
        wkv1[idx]  = f2tff(kv1w[idx]);
        wproj[idx] = f2tff(projw[idx]);
    }
    if (idx < 16384) lmacc[idx] = 0.f;
    if (idx < 4096)  gacc[idx]  = 0.f;
}

// ---------------- pipelined tf32 GEMM core (device function) ----------------
// C = ((A (+A2)) @ Bw + bias) * oscale ; Bw pre-rounded tf32.
// Block tile 128x128, 8 warps (2x4), warp 64x32, kc=32.
// XCOL: A is x[B,4096,256] addressed through the 2x2/s2 im2col map (K=1024).
template<int FUSE, int XCOL>
__device__ __forceinline__ void gemm_core(
    const float* __restrict__ A, const float* __restrict__ A2,
    const float* __restrict__ Bw, const float* __restrict__ bias,
    float* __restrict__ C, int K, int Nn, float oscale, int oround,
    int bx, int by, float* smx)
{
    float* As = smx;                   // [2][128*36]
    float* Bs = smx + 2 * 4608;        // [2][32*136]
    float* biass = smx + 2 * 4608 + 2 * 4352;  // [128]
    const int tid = threadIdx.x, warp = tid >> 5, lane = tid & 31;
    const int m0 = by * 128, n0 = bx * 128;
    const int wm = (warp & 1) * 64, wn = (warp >> 1) * 32;
    if (tid < 128) biass[tid] = bias[n0 + tid];

    float acc[4][4][4];
#pragma unroll
    for (int i = 0; i < 4; ++i)
#pragma unroll
        for (int j = 0; j < 4; ++j)
#pragma unroll
            for (int k = 0; k < 4; ++k) acc[i][j][k] = 0.f;

    const int am = tid >> 1, akb = (tid & 1) * 16;
    const int bk = tid >> 3, bnb = (tid & 7) * 16;
    const int row = m0 + am;
    // XCOL precompute
    const int xb = row >> 10, xm = row & 1023;
    const int ii2 = (xm >> 5) << 1, jj2 = (xm & 31) << 1;
    const int basepix = xb << 12;

    const float* Ap  = A + (size_t)row * K + akb;
    const float* A2p = FUSE ? (A2 + (size_t)row * K + akb) : (const float*)0;
    const float* Bp  = Bw + (size_t)bk * Nn + n0 + bnb;
    const unsigned BsW = sptr(Bs) + (bk * 136 + bnb) * 4;

    float4 ar[4], ar2[4];
#pragma unroll
    for (int i = 0; i < 4; ++i) {
        if (XCOL) {
            int k = akb + i * 4, f = k >> 8, cc = k & 255;
            int n = ((ii2 + (f >> 1)) << 6) + jj2 + (f & 1);
            ar[i] = *(const float4*)&A[(size_t)(basepix + n) * 256 + cc];
        } else {
            ar[i] = *(const float4*)(Ap + i * 4);
        }
    }
    if (FUSE) {
#pragma unroll
        for (int i = 0; i < 4; ++i) ar2[i] = *(const float4*)(A2p + i * 4);
    }
#pragma unroll
    for (int i = 0; i < 4; ++i) CPA(BsW + i * 16, Bp + i * 4);
    CPC();

    const int nc = K >> 5;
    for (int c = 0; c < nc; ++c) {
        const int buf = c & 1;
        CPW(0);
        {
            float* dst = As + buf * 4608 + am * 36 + akb;
#pragma unroll
            for (int i = 0; i < 4; ++i) {
                float4 v = ar[i];
                if (FUSE) { float4 w = ar2[i]; v.x += w.x; v.y += w.y; v.z += w.z; v.w += w.w; }
                dst[i * 4 + 0] = f2tff(v.x); dst[i * 4 + 1] = f2tff(v.y);
                dst[i * 4 + 2] = f2tff(v.z); dst[i * 4 + 3] = f2tff(v.w);
            }
        }
        __syncthreads();
        if (c + 1 < nc) {
            const float* bp = Bp + (size_t)(c + 1) * 32 * Nn;
            unsigned w = BsW + (buf ^ 1) * (4352 * 4);
#pragma unroll
            for (int i = 0; i < 4; ++i) CPA(w + i * 16, bp + i * 4);
            CPC();
#pragma unroll
            for (int i = 0; i < 4; ++i) {
                if (XCOL) {
                    int k = (c + 1) * 32 + akb + i * 4, f = k >> 8, cc = k & 255;
                    int n = ((ii2 + (f >> 1)) << 6) + jj2 + (f & 1);
                    ar[i] = *(const float4*)&A[(size_t)(basepix + n) * 256 + cc];
                } else {
                    ar[i] = *(const float4*)(Ap + (c + 1) * 32 + i * 4);
                }
            }
            if (FUSE) {
                const float* a2p = A2p + (c + 1) * 32;
#pragma unroll
                for (int i = 0; i < 4; ++i) ar2[i] = *(const float4*)(a2p + i * 4);
            }
        }
        const float* Ab = As + buf * 4608;
        const float* Bb = Bs + buf * 4352;
#pragma unroll
        for (int ks = 0; ks < 4; ++ks) {
            unsigned a[4][4], bfr[4][2];
#pragma unroll
            for (int mt = 0; mt < 4; ++mt) {
                int r = wm + mt * 16 + (lane >> 2), cc = ks * 8 + (lane & 3);
                a[mt][0] = __float_as_uint(Ab[r * 36 + cc]);
                a[mt][1] = __float_as_uint(Ab[(r + 8) * 36 + cc]);
                a[mt][2] = __float_as_uint(Ab[r * 36 + cc + 4]);
                a[mt][3] = __float_as_uint(Ab[(r + 8) * 36 + cc + 4]);
            }
#pragma unroll
            for (int nt = 0; nt < 4; ++nt) {
                int n = wn + nt * 8 + (lane >> 2), kr = ks * 8 + (lane & 3);
                bfr[nt][0] = __float_as_uint(Bb[kr * 136 + n]);
                bfr[nt][1] = __float_as_uint(Bb[(kr + 4) * 136 + n]);
            }
#pragma unroll
            for (int mt = 0; mt < 4; ++mt)
#pragma unroll
                for (int nt = 0; nt < 4; ++nt) mma8(acc[mt][nt], a[mt], bfr[nt]);
        }
    }

#pragma unroll
    for (int mt = 0; mt < 4; ++mt) {
        int r = m0 + wm + mt * 16 + (lane >> 2);
#pragma unroll
        for (int nt = 0; nt < 4; ++nt) {
            int cc = wn + nt * 8 + (lane & 3) * 2;
            float o0 = (acc[mt][nt][0] + biass[cc]) * oscale;
            float o1 = (acc[mt][nt][1] + biass[cc + 1]) * oscale;
            float o2 = (acc[mt][nt][2] + biass[cc]) * oscale;
            float o3 = (acc[mt][nt][3] + biass[cc + 1]) * oscale;
            if (oround) { o0 = f2tff(o0); o1 = f2tff(o1); o2 = f2tff(o2); o3 = f2tff(o3); }
            *(float2*)&C[(size_t)r * Nn + n0 + cc] = make_float2(o0, o1);
            *(float2*)&C[(size_t)(r + 8) * Nn + n0 + cc] = make_float2(o2, o3);
        }
    }
}

// ---------------- mega1: big linear GEMM (N=768) || sr conv GEMM (fused im2col) ----------------
__global__ __launch_bounds__(256, 2) void mega1_kernel(
    const float* __restrict__ x,
    const float* __restrict__ wbig, const float* __restrict__ bbig, float* __restrict__ big,
    const float* __restrict__ srwt, const float* __restrict__ srb, float* __restrict__ xs)
{
    extern __shared__ float smx[];
    if (blockIdx.x < 6) {
        gemm_core<0, 0>(x, nullptr, wbig, bbig, big, 256, 768, 1.f, 1,
                        blockIdx.x, blockIdx.y, smx);
    } else if (blockIdx.y < 32) {
        gemm_core<0, 1>(x, nullptr, srwt, srb, xs, 1024, 256, 1.f, 0,
                        blockIdx.x - 6, blockIdx.y, smx);
    }
}

// ---------------- kv1 GEMM ----------------
__global__ __launch_bounds__(256, 2) void kv1_kernel(
    const float* __restrict__ xs, const float* __restrict__ wkv1,
    const float* __restrict__ kv1b, float* __restrict__ kv1)
{
    extern __shared__ float smx[];
    gemm_core<0, 0>(xs, nullptr, wkv1, kv1b, kv1, 256, 256, 1.f, 1,
                    blockIdx.x, blockIdx.y, smx);
}

// ---------------- mega2: attn2 || dwconv || LN+GELU (all depend only on mega1) ----------------
// grid: [0,512) attn2 (128 active threads), [512,4608) dwconv, [4608,8704) lngelu
__global__ __launch_bounds__(256) void mega2_kernel(
    float* __restrict__ xs, const float* __restrict__ normw, const float* __restrict__ normb,
    const float* __restrict__ big, const float* __restrict__ cw, const float* __restrict__ cb,
    float* __restrict__ lepe, float* __restrict__ att_out, float* __restrict__ lmacc)
{
    extern __shared__ float sm2[];
    const int bid = blockIdx.x;
    const int tid = threadIdx.x;

    if (bid < 512) {
        // ---- attn2: 8 windows x 16 threads, intra-warp sync only ----
        if (tid >= 128) return;
        float* ks = sm2;                 // [8][16][33]
        float* vs = sm2 + 8 * 528;       // [8][16][33]
        float* ps = sm2 + 16 * 528;      // [8][16][17]
        const int g = tid >> 4, t = tid & 15;
        const int w = (bid << 3) + g;
        const int b = w >> 10, h = (w >> 8) & 3, win = w & 255;
        const int wy = win >> 4, wx = win & 15;
        const int n = ((wy << 2) + (t >> 2)) * 64 + (wx << 2) + (t & 3);

        const float* row = &big[((size_t)(b * 4096 + n)) * 768];
        float qr[32];
#pragma unroll
        for (int dd = 0; dd < 32; ++dd) {
            ks[(g * 16 + t) * 33 + dd] = row[256 + h * 32 + dd];
            vs[(g * 16 + t) * 33 + dd] = row[384 + h * 32 + dd];
            qr[dd] = row[128 + h * 32 + dd];
        }
        __syncwarp(0xffffffffu);

        float s[16];
        float mx = -1e30f;
#pragma unroll
        for (int m = 0; m < 16; ++m) {
            float a = 0.f;
#pragma unroll
            for (int dd = 0; dd < 32; ++dd) a += qr[dd] * ks[(g * 16 + m) * 33 + dd];
            s[m] = a * SCALE;
            mx = fmaxf(mx, s[m]);
        }
        float sum = 0.f;
#pragma unroll
        for (int m = 0; m < 16; ++m) { s[m] = __expf(s[m] - mx); sum += s[m]; }
        float inv = 1.f / sum;

        float o[32];
#pragma unroll
        for (int dd = 0; dd < 32; ++dd) o[dd] = 0.f;
#pragma unroll
        for (int m = 0; m < 16; ++m) {
            float p = s[m] * inv;
            ps[(g * 16 + t) * 17 + m] = p;
#pragma unroll
            for (int dd = 0; dd < 32; ++dd) o[dd] += p * vs[(g * 16 + m) * 33 + dd];
        }
        float* orow = &att_out[((size_t)(b * 4096 + n)) * 256 + 128 + h * 32];
#pragma unroll
        for (int dd = 0; dd < 32; ++dd) orow[dd] = o[dd];
        __syncwarp(0xffffffffu);

        float cs = 0.f;
#pragma unroll
        for (int qq = 0; qq < 16; ++qq) cs += ps[(g * 16 + qq) * 17 + t];
        atomicAdd(&lmacc[((b << 8) + win) * 16 + t], cs);
    } else if (bid < 4608) {
        // ---- dwconv: lepe depthwise 3x3, float4 over channels ----
        int idx = (bid - 512) * 256 + tid;  // BB*NN*64
        int c4 = idx & 63;
        int n = (idx >> 6) & 4095;
        int b = idx >> 18;
        int y = n >> 6, x = n & 63;
        int c = c4 << 2;
        float4 acc = make_float4(cb[c], cb[c + 1], cb[c + 2], cb[c + 3]);
#pragma unroll
        for (int dy = 0; dy < 3; ++dy) {
            int yy = y + dy - 1;
            if ((unsigned)yy >= 64u) continue;
#pragma unroll
            for (int dx = 0; dx < 3; ++dx) {
                int xx = x + dx - 1;
                if ((unsigned)xx >= 64u) continue;
                float4 v = *(const float4*)&big[((size_t)((b << 12) + (yy << 6) + xx)) * 768 + 512 + c];
                int wi = dy * 3 + dx;
                acc.x += v.x * cw[(c + 0) * 9 + wi];
                acc.y += v.y * cw[(c + 1) * 9 + wi];
                acc.z += v.z * cw[(c + 2) * 9 + wi];
                acc.w += v.w * cw[(c + 3) * 9 + wi];
            }
        }
        *(float4*)&lepe[((size_t)((b << 12) + n)) * 256 + c] = acc;
    } else {
        // ---- LayerNorm + exact GELU, one row per block ----
        int r = bid - 4608;
        float v = xs[(size_t)r * 256 + tid];
        float s = v, s2 = v * v;
#pragma unroll
        for (int o = 16; o; o >>= 1) {
            s  += __shfl_xor_sync(0xffffffffu, s,  o);
            s2 += __shfl_xor_sync(0xffffffffu, s2, o);
        }
        float* ws  = sm2;
        float* ws2 = sm2 + 8;
        if ((tid & 31) == 0) { ws[tid >> 5] = s; ws2[tid >> 5] = s2; }
        __syncthreads();
        float ts = 0.f, ts2 = 0.f;
#pragma unroll
        for (int i = 0; i < 8; ++i) { ts += ws[i]; ts2 += ws2[i]; }
        float mean = ts * (1.f / 256.f);
        float var = ts2 * (1.f / 256.f) - mean * mean;
        float y = (v - mean) * rsqrtf(var + 1e-5f) * normw[tid] + normb[tid];
        xs[(size_t)r * 256 + tid] = 0.5f * y * (1.0f + erff(y * 0.70710678118654752f));
    }
}

// ---------------- branch 1: SR global attention (pipelined, unchanged) ----------------
#define S_STR 1036
#define A1_SMEM_FLOATS 47872

__global__ __launch_bounds__(256) void attn1_tc(
    const float* __restrict__ q1, const float* __restrict__ kv1,
    float* __restrict__ att_out, float* __restrict__ gacc)
{
    extern __shared__ float sm[];
    float* S  = sm;
    float* qs = sm + 33152;
    float* kv = sm + 34304;
    float* op = sm + 43520;

    const int tid = threadIdx.x, warp = tid >> 5, lane = tid & 31;
    const int bh = blockIdx.y, b = bh >> 2, h = bh & 3;
    const int q0 = blockIdx.x * 32;
    const int wq = warp & 1, wk = warp >> 1;

    {
        int q = tid >> 3, d4 = (tid & 7) * 4;
        float4 v = *(const float4*)&q1[(size_t)(b * 4096 + q0 + q) * 768 + h * 32 + d4];
        float* p = &qs[q * 36 + d4];
        p[0] = v.x; p[1] = v.y; p[2] = v.z; p[3] = v.w;
    }
    const int jj = tid >> 1, db = (tid & 1) * 16;
    const size_t kbase = (size_t)(b * 1024) * 256 + h * 32;
    const size_t vbase = kbase + 128;
    const unsigned kvW = sptr(kv) + (jj * 36 + db) * 4;
    {
        const float* src = kv1 + kbase + (size_t)jj * 256 + db;
#pragma unroll
        for (int i = 0; i < 4; ++i) CPA(kvW + i * 16, src + i * 4);
        CPC();
    }
    __syncthreads();

    unsigned qa[4][4];
#pragma unroll
    for (int ks = 0; ks < 4; ++ks) {
        int r = wq * 16 + (lane >> 2), cc = ks * 8 + (lane & 3);
        qa[ks][0] = __float_as_uint(qs[r * 36 + cc]);
        qa[ks][1] = __float_as_uint(qs[(r + 8) * 36 + cc]);
        qa[ks][2] = __float_as_uint(qs[r * 36 + cc + 4]);
        qa[ks][3] = __float_as_uint(qs[(r + 8) * 36 + cc + 4]);
    }

    for (int ch = 0; ch < 8; ++ch) {
        const int buf = ch & 1;
        CPW(0);
        __syncthreads();
        if (ch < 7) {
            const float* src = kv1 + kbase + (size_t)((ch + 1) * 128 + jj) * 256 + db;
            unsigned w = kvW + (buf ^ 1) * (4608 * 4);
#pragma unroll
            for (int i = 0; i < 4; ++i) CPA(w + i * 16, src + i * 4);
            CPC();
        }
        const float* kb = kv + buf * 4608;
        float c4[4][4];
#pragma unroll
        for (int nt = 0; nt < 4; ++nt)
#pragma unroll
            for (int k = 0; k < 4; ++k) c4[nt][k] = 0.f;
#pragma unroll
        for (int ks = 0; ks < 4; ++ks) {
#pragma unroll
            for (int nt = 0; nt < 4; ++nt) {
                int n = wk * 32 + nt * 8 + (lane >> 2), dr = ks * 8 + (lane & 3);
                unsigned bb2[2] = { __float_as_uint(kb[n * 36 + dr]),
                                    __float_as_uint(kb[n * 36 + dr + 4]) };
                mma8(c4[nt], qa[ks], bb2);
            }
        }
#pragma unroll
        for (int nt = 0; nt < 4; ++nt) {
            int r = wq * 16 + (lane >> 2);
            int col = ch * 128 + wk * 32 + nt * 8 + (lane & 3) * 2;
            *(float2*)&S[r * S_STR + col] = make_float2(c4[nt][0] * SCALE, c4[nt][1] * SCALE);
            *(float2*)&S[(r + 8) * S_STR + col] = make_float2(c4[nt][2] * SCALE, c4[nt][3] * SCALE);
        }
    }
    __syncthreads();

    {
        const float* src = kv1 + vbase + (size_t)jj * 256 + db;
#pragma unroll
        for (int i = 0; i < 4; ++i) CPA(kvW + i * 16, src + i * 4);
        CPC();
    }

#pragma unroll
    for (int rr = 0; rr < 4; ++rr) {
        int r = warp * 4 + rr;
        float v[32];
        float mx = -1e30f;
#pragma unroll
        for (int i = 0; i < 32; ++i) { v[i] = S[r * S_STR + lane + 32 * i]; mx = fmaxf(mx, v[i]); }
#pragma unroll
        for (int o = 16; o; o >>= 1) mx = fmaxf(mx, __shfl_xor_sync(0xffffffffu, mx, o));
        float ssum = 0.f;
#pragma unroll
        for (int i = 0; i < 32; ++i) { v[i] = __expf(v[i] - mx); ssum += v[i]; }
#pragma unroll
        for (int o = 16; o; o >>= 1) ssum += __shfl_xor_sync(0xffffffffu, ssum, o);
        float inv = 1.f / ssum;
#pragma unroll
        for (int i = 0; i < 32; ++i) S[r * S_STR + lane + 32 * i] = f2tff(v[i] * inv);
    }
    __syncthreads();

    {
        float cs[4] = {0.f, 0.f, 0.f, 0.f};
        for (int r = 0; r < 32; ++r)
#pragma unroll
            for (int j = 0; j < 4; ++j) cs[j] += S[r * S_STR + tid + 256 * j];
#pragma unroll
        for (int j = 0; j < 4; ++j) atomicAdd(&gacc[(b << 10) + tid + 256 * j], cs[j]);
    }

    float o4[4][4];
#pragma unroll
    for (int nt = 0; nt < 4; ++nt)
#pragma unroll
        for (int k = 0; k < 4; ++k) o4[nt][k] = 0.f;

    const int wr = warp >> 1;
    for (int ch = 0; ch < 8; ++ch) {
        const int buf = ch & 1;
        CPW(0);
        __syncthreads();
        if (ch < 7) {
            const float* src = kv1 + vbase + (size_t)((ch + 1) * 128 + jj) * 256 + db;
            unsigned w = kvW + (buf ^ 1) * (4608 * 4);
#pragma unroll
            for (int i = 0; i < 4; ++i) CPA(w + i * 16, src + i * 4);
            CPC();
        }
        const float* vb = kv + buf * 4608;
#pragma unroll
        for (int ks = 0; ks < 4; ++ks) {
            int jb = ch * 128 + wr * 32 + ks * 8;
            int r = wq * 16 + (lane >> 2), c = jb + (lane & 3);
            unsigned a[4] = { __float_as_uint(S[r * S_STR + c]),
                              __float_as_uint(S[(r + 8) * S_STR + c]),
                              __float_as_uint(S[r * S_STR + c + 4]),
                              __float_as_uint(S[(r + 8) * S_STR + c + 4]) };
            int jl = wr * 32 + ks * 8 + (lane & 3);
#pragma unroll
            for (int nt = 0; nt < 4; ++nt) {
                int d = nt * 8 + (lane >> 2);
                unsigned bb2[2] = { __float_as_uint(vb[jl * 36 + d]),
                                    __float_as_uint(vb[(jl + 4) * 36 + d]) };
                mma8(o4[nt], a, bb2);
            }
        }
    }

#pragma unroll
    for (int nt = 0; nt < 4; ++nt) {
        int rr = lane >> 2, col = nt * 8 + (lane & 3) * 2;
        *(float2*)&op[warp * 544 + rr * 34 + col] = make_float2(o4[nt][0], o4[nt][1]);
        *(float2*)&op[warp * 544 + (rr + 8) * 34 + col] = make_float2(o4[nt][2], o4[nt][3]);
    }
    __syncthreads();
#pragma unroll
    for (int i = 0; i < 4; ++i) {
        int idx = tid + 256 * i;
        int q = idx >> 5, d = idx & 31;
        int wq2 = q >> 4, ql = q & 15;
        float s = op[(0 + wq2) * 544 + ql * 34 + d] + op[(2 + wq2) * 544 + ql * 34 + d]
                + op[(4 + wq2) * 544 + ql * 34 + d] + op[(6 + wq2) * 544 + ql * 34 + d];
        att_out[(size_t)(b * 4096 + q0 + q) * 256 + h * 32 + d] = s;
    }
}

// ---------------- projmask: final projection GEMM || mask assembly ----------------
__global__ __launch_bounds__(256, 2) void projmask_kernel(
    const float* __restrict__ att, const float* __restrict__ lepe,
    const float* __restrict__ wproj, const float* __restrict__ projb,
    float* __restrict__ out,
    const float* __restrict__ gacc, const float* __restrict__ lmacc)
{
    extern __shared__ float smx[];
    if (blockIdx.x < 2) {
        gemm_core<1, 0>(att, lepe, wproj, projb, out, 256, 256, 2.f, 0,
                        blockIdx.x, blockIdx.y, smx);
    } else if (blockIdx.y < 64) {
        int idx = blockIdx.y * 256 + threadIdx.x;  // BB*NN / 4... 16384 total
        int b = idx >> 12, n = idx & 4095;
        int y = n >> 6, x = n & 63;
        float gv = gacc[(b << 10) + ((y >> 1) << 5) + (x >> 1)] * (1.f / 16384.f);
        float lv = lmacc[((b << 8) + ((y >> 2) << 4) + (x >> 2)) * 16 + ((y & 3) << 2) + (x & 3)] * (1.f / 64.f);
        float m = gv + lv;
        out[4194304 + (b << 12) + (y << 6) + x] = m;
        out[4210688 + (b << 12) + (x << 6) + y] = m;
    }
}

// ---------------- host launcher ----------------
extern "C" void kernel_launch(void* const* d_in, const int* in_sizes, int n_in,
                              void* d_out, int out_size)
{
    const float* x        = (const float*)d_in[0];
    const float* q1_w     = (const float*)d_in[1];
    const float* q1_b     = (const float*)d_in[2];
    const float* kv1_w    = (const float*)d_in[3];
    const float* kv1_b    = (const float*)d_in[4];
    const float* q2_w     = (const float*)d_in[5];
    const float* q2_b     = (const float*)d_in[6];
    const float* kv2_w    = (const float*)d_in[7];
    const float* kv2_b    = (const float*)d_in[8];
    const float* lepe_w   = (const float*)d_in[9];
    const float* lepe_b   = (const float*)d_in[10];
    const float* lepe_cw  = (const float*)d_in[11];
    const float* lepe_cb  = (const float*)d_in[12];
    const float* sr_w     = (const float*)d_in[13];
    const float* sr_b     = (const float*)d_in[14];
    const float* norm_w   = (const float*)d_in[15];
    const float* norm_b   = (const float*)d_in[16];
    const float* proj_w   = (const float*)d_in[17];
    const float* proj_b   = (const float*)d_in[18];
    float* out = (float*)d_out;

    float *p_big, *p_lepe, *p_srwt, *p_xs, *p_kv1, *p_att, *p_g, *p_lm;
    float *p_wbig, *p_bbig, *p_wkv1, *p_wproj;
    cudaGetSymbolAddress((void**)&p_big,   g_big);
    cudaGetSymbolAddress((void**)&p_lepe,  g_lepe);
    cudaGetSymbolAddress((void**)&p_srwt,  g_srwt);
    cudaGetSymbolAddress((void**)&p_xs,    g_xs);
    cudaGetSymbolAddress((void**)&p_kv1,   g_kv1);
    cudaGetSymbolAddress((void**)&p_att,   g_att);
    cudaGetSymbolAddress((void**)&p_g,     g_gacc);
    cudaGetSymbolAddress((void**)&p_lm,    g_lmacc);
    cudaGetSymbolAddress((void**)&p_wbig,  g_wbig);
    cudaGetSymbolAddress((void**)&p_bbig,  g_bbig);
    cudaGetSymbolAddress((void**)&p_wkv1,  g_wkv1);
    cudaGetSymbolAddress((void**)&p_wproj, g_wproj);

    const int gsm = (2 * 4608 + 2 * 4352 + 128) * (int)sizeof(float);  // 72192 B
    cudaFuncSetAttribute(mega1_kernel,    cudaFuncAttributeMaxDynamicSharedMemorySize, gsm);
    cudaFuncSetAttribute(kv1_kernel,      cudaFuncAttributeMaxDynamicSharedMemorySize, gsm);
    cudaFuncSetAttribute(projmask_kernel, cudaFuncAttributeMaxDynamicSharedMemorySize, gsm);
    const int a1sm = A1_SMEM_FLOATS * (int)sizeof(float);  // 191488 B
    cudaFuncSetAttribute(attn1_tc, cudaFuncAttributeMaxDynamicSharedMemorySize, a1sm);
    const int m2sm = (16 * 528 + 8 * 272) * (int)sizeof(float);  // 42496 B (attn2 region)

    // 1. fused prep (weights + accumulator zero)
    prep_kernel<<<1024, 256>>>(q1_w, q2_w, kv2_w, lepe_w, q1_b, q2_b, kv2_b, lepe_b,
                               kv1_w, proj_w, sr_w,
                               p_wbig, p_bbig, p_wkv1, p_wproj, p_srwt, p_g, p_lm);

    // 2. big linear GEMM (x @ [q1|q2|kv2|lepe]) || sr conv GEMM (im2col fused)
    mega1_kernel<<<dim3(8, 128), 256, gsm>>>(x, p_wbig, p_bbig, p_big, p_srwt, sr_b, p_xs);

    // 3. attn2 || dwconv || LN+GELU
    mega2_kernel<<<8704, 256, m2sm>>>(p_xs, norm_w, norm_b, p_big, lepe_cw, lepe_cb,
                                      p_lepe, p_att, p_lm);

    // 4. kv1 GEMM
    kv1_kernel<<<dim3(2, 32), 256, gsm>>>(p_xs, p_wkv1, kv1_b, p_kv1);

    // 5. SR attention
    attn1_tc<<<dim3(128, 16), 256, a1sm>>>(p_big, p_kv1, p_att, p_g);

    // 6. projection GEMM (out = 2*((att+lepe)@proj_w+proj_b)) || mask assembly
    projmask_kernel<<<dim3(3, 128), 256, gsm>>>(p_att, p_lepe, p_wproj, proj_b, out, p_g, p_lm);
}